// round 11
// baseline (speedup 1.0000x reference)
#include <cuda_runtime.h>
#include <cuda_bf16.h>
#include <math.h>
#include <stdint.h>

#define BB 8
#define CIN 512
#define C1 256
#define DD 128
#define KK 32
#define NN 9216
#define ROWS (BB*NN)
#define GS 18            // Gram split-K slices
typedef __nv_bfloat16 bf16;
typedef unsigned int u32;

// ------------- scratch (device globals) -------------
__device__ bf16 g_Xh[ROWS*CIN], g_Xm[ROWS*CIN], g_Xl[ROWS*CIN];      // X (N-major rows n, k contig)
__device__ bf16 g_Xch[ROWS*CIN], g_Xcm[ROWS*CIN], g_Xcl[ROWS*CIN];   // X (C-major rows ch, n contig)
__device__ bf16 g_Wth[C1*CIN], g_Wtm[C1*CIN], g_Wtl[C1*CIN];
__device__ bf16 g_Wph[C1*CIN], g_Wpm[C1*CIN], g_Wpl[C1*CIN];
__device__ bf16 g_WgTh[CIN*C1], g_WgTm[CIN*C1];                      // Wg transposed (k rows, d contig)
__device__ bf16 g_W2h[CIN*C1], g_W2m[CIN*C1];
__device__ bf16 g_W3h[DD*CIN], g_W3m[DD*CIN];
__device__ float g_Gp[(BB*GS)*CIN*CIN];                              // Gram split-K partials
__device__ bf16 g_GRh[BB*CIN*CIN], g_GRm[BB*CIN*CIN], g_GRl[BB*CIN*CIN];
__device__ float g_T1p[BB*4*C1*CIN];                                 // T1 split-K partials
__device__ bf16 g_T1h[BB*C1*CIN], g_T1m[BB*C1*CIN], g_T1l[BB*C1*CIN];
__device__ float g_Fp4[BB*4*C1*C1];                                  // f split-K partials
__device__ bf16 g_Fh[BB*C1*C1], g_Fm[BB*C1*C1];                      // f^T parts (d rows, c contig)
__device__ bf16 g_Wfh[BB*CIN*C1], g_Wfm[BB*CIN*C1];                  // Wf = W2·f (cc rows, d contig)
__device__ float g_Mf[BB*CIN*CIN];                                   // M fp32 (k rows, cc contig)
__device__ bf16 g_Mkh[BB*CIN*CIN], g_Mkm[BB*CIN*CIN];                // M (k rows, cc contig)
__device__ bf16 g_Mch[BB*CIN*CIN], g_Mcm[BB*CIN*CIN];                // M^T (cc rows, k contig)
__device__ bf16 g_M2h[BB*DD*CIN], g_M2m[BB*DD*CIN];                  // M2^T (d rows, k contig)
__device__ float g_b2e[BB*CIN];                                      // b2 + Wf·bg
__device__ float g_b3e[BB*DD];                                       // W3·b2e + b3
__device__ float g_Zct[ROWS*CIN];                                    // z in (B,C,N)
__device__ float g_ZDt[ROWS*DD];                                     // z_ rows n, d contig
__device__ float g_sx[BB*CIN];
__device__ float g_bth[BB*C1], g_bph[BB*C1];
__device__ float g_Eacc[BB*KK*DD], g_Asum[BB*KK], g_Es[BB*DD], g_gam[BB*CIN];

// ------------- helpers -------------
__device__ __forceinline__ u32 smem_u32(const void* p) {
    u32 a;
    asm("{ .reg .u64 t; cvta.to.shared.u64 t, %1; cvt.u32.u64 %0, t; }" : "=r"(a) : "l"(p));
    return a;
}
__device__ __forceinline__ void cp16(u32 d, const void* s) {
    asm volatile("cp.async.cg.shared.global [%0], [%1], 16;" :: "r"(d), "l"(s));
}
__device__ __forceinline__ void cp_commit() { asm volatile("cp.async.commit_group;" ::: "memory"); }
template<int N> __device__ __forceinline__ void cp_waitg() {
    asm volatile("cp.async.wait_group %0;" :: "n"(N) : "memory");
}
__device__ __forceinline__ void ldm_x4(u32* r, u32 addr) {
    asm volatile("ldmatrix.sync.aligned.m8n8.x4.shared.b16 {%0,%1,%2,%3}, [%4];"
        : "=r"(r[0]), "=r"(r[1]), "=r"(r[2]), "=r"(r[3]) : "r"(addr));
}
__device__ __forceinline__ void mma16816(float* d, const u32* a, const u32* b) {
    asm volatile(
        "mma.sync.aligned.m16n8k16.row.col.f32.bf16.bf16.f32 "
        "{%0,%1,%2,%3}, {%4,%5,%6,%7}, {%8,%9}, {%0,%1,%2,%3};"
        : "+f"(d[0]), "+f"(d[1]), "+f"(d[2]), "+f"(d[3])
        : "r"(a[0]), "r"(a[1]), "r"(a[2]), "r"(a[3]), "r"(b[0]), "r"(b[1]));
}
__device__ __forceinline__ void st2bf(bf16* p, long i, float a, float b_) {
    __nv_bfloat162 v(__float2bfloat16(a), __float2bfloat16(b_));
    *(u32*)(p + i) = *(u32*)&v;
}

// ============ mma.sync bf16-split GEMM, product-shared tiles, BK=32 ============
// C[z; m, n] = sum over triangular products A_pa * B_pb (pa+pb<NB), K-major.
// SYM: blockIdx.x indexes lower-triangle 128x128 tile pairs of a 512x512 output.
template<int NPROD, bool SYM>
__global__ __launch_bounds__(256, 2) void mma_gemm(
    const bf16* __restrict__ Ah, const bf16* __restrict__ Am, const bf16* __restrict__ Al,
    int lda, long sAb,
    const bf16* __restrict__ Bh, const bf16* __restrict__ Bm, const bf16* __restrict__ Bl,
    int ldb, long sBb,
    float* __restrict__ C, bf16* __restrict__ Ch, bf16* __restrict__ Cm,
    int ldc, long sCz,
    const float* __restrict__ biasC, long sBC,
    const float* __restrict__ biasR, long sBR,
    const float* __restrict__ Rf, long sRz,
    int NCH, int S)
{
    constexpr int NA = (NPROD == 6) ? 3 : 2;
    constexpr int NB = NA;
    constexpr int STAGE = (NA + NB) * 8192;

    extern __shared__ __align__(16) char smem[];
    const u32 sbase = smem_u32(smem);

    const int tid = threadIdx.x, lane = tid & 31, wid = tid >> 5;
    const int wm = wid & 1, wn = wid >> 1;
    const int z = blockIdx.z, b = z / S, s = z % S;
    int bx, by;
    if (SYM) {
        int p = blockIdx.x;
        by = (p < 1) ? 0 : (p < 3) ? 1 : (p < 6) ? 2 : 3;
        bx = p - (by * (by + 1)) / 2;
    } else { bx = blockIdx.x; by = blockIdx.y; }
    const long m0 = (long)by * 128;
    const int n0 = bx * 128;
    const int KS = NCH * 32;

    const long abase = (long)b * sAb + m0 * lda + (long)s * KS;
    const long bbase = (long)b * sBb + (long)n0 * ldb + (long)s * KS;

    const bf16* APT[3] = {Ah, Am, Al};
    const bf16* BPT[3] = {Bh, Bm, Bl};

    float acc[4][4][4];
#pragma unroll
    for (int i = 0; i < 4; i++)
#pragma unroll
        for (int j = 0; j < 4; j++)
#pragma unroll
            for (int r = 0; r < 4; r++) acc[i][j][r] = 0.f;

    const int row2 = tid >> 1, lq = tid & 1;
    const int sw = (row2 >> 1) & 3;
    const u32 c0off = (u32)(row2 * 64 + (((lq * 2 + 0) ^ sw) << 4));
    const u32 c1off = (u32)(row2 * 64 + (((lq * 2 + 1) ^ sw) << 4));

    auto issue = [&](int c) {
        int k0 = c * 32;
        u32 sd = sbase + (c & 1) * STAGE;
#pragma unroll
        for (int p = 0; p < NA; p++) {
            const bf16* ap = APT[p] + abase + k0 + (long)row2 * lda + lq * 16;
            cp16(sd + p * 8192 + c0off, ap);
            cp16(sd + p * 8192 + c1off, ap + 8);
        }
#pragma unroll
        for (int p = 0; p < NB; p++) {
            const bf16* bp = BPT[p] + bbase + k0 + (long)row2 * ldb + lq * 16;
            cp16(sd + (NA + p) * 8192 + c0off, bp);
            cp16(sd + (NA + p) * 8192 + c1off, bp + 8);
        }
        cp_commit();
    };

    u32 aoff[4], boff[2];
#pragma unroll
    for (int t = 0; t < 4; t++) {
        int ra = wm * 64 + t * 16 + (lane & 15);
        int j = lane >> 4;
        aoff[t] = (u32)(ra * 64 + ((j ^ ((ra >> 1) & 3)) << 4));
    }
#pragma unroll
    for (int u = 0; u < 2; u++) {
        int rb = wn * 32 + u * 16 + (lane & 7) + ((lane >> 4) & 1) * 8;
        int j = (lane >> 3) & 1;
        boff[u] = (u32)(rb * 64 + ((j ^ ((rb >> 1) & 3)) << 4));
    }

    issue(0);
    for (int c = 0; c < NCH; c++) {
        if (c + 1 < NCH) { issue(c + 1); cp_waitg<1>(); }
        else cp_waitg<0>();
        __syncthreads();
        u32 sA = sbase + (c & 1) * STAGE;
        u32 sB = sA + NA * 8192;
#pragma unroll
        for (int kk = 0; kk < 2; kk++) {
            u32 kx = kk << 5;
            u32 bfr[NB][2][4];
#pragma unroll
            for (int pb = 0; pb < NB; pb++)
#pragma unroll
                for (int u = 0; u < 2; u++)
                    ldm_x4(bfr[pb][u], sB + pb * 8192 + (boff[u] ^ kx));
#pragma unroll
            for (int pa = 0; pa < NA; pa++) {
                u32 af[4][4];
#pragma unroll
                for (int t = 0; t < 4; t++)
                    ldm_x4(af[t], sA + pa * 8192 + (aoff[t] ^ kx));
#pragma unroll
                for (int pb = 0; pb < NB; pb++) {
                    if (pa + pb < NB) {
#pragma unroll
                        for (int mi = 0; mi < 4; mi++)
#pragma unroll
                            for (int ni = 0; ni < 4; ni++)
                                mma16816(acc[mi][ni], af[mi], &bfr[pb][ni >> 1][(ni & 1) * 2]);
                    }
                }
            }
        }
        __syncthreads();
    }

    // ---- epilogue ----
    const int mrow = lane >> 2, nc2 = (lane & 3) * 2;
#pragma unroll
    for (int mi = 0; mi < 4; mi++) {
#pragma unroll
        for (int rp = 0; rp < 2; rp++) {
            long row = m0 + wm * 64 + mi * 16 + mrow + rp * 8;
            long coff = (long)z * sCz + row * ldc;
            long roff = (long)b * sRz + row * ldc;
            float br = biasR ? biasR[b * sBR + row] : 0.f;
#pragma unroll
            for (int ni = 0; ni < 4; ni++) {
                int col = n0 + wn * 32 + ni * 8 + nc2;
                float v0 = acc[mi][ni][rp * 2 + 0] + br;
                float v1 = acc[mi][ni][rp * 2 + 1] + br;
                if (biasC) { v0 += biasC[b * sBC + col]; v1 += biasC[b * sBC + col + 1]; }
                if (Rf) {
                    float2 r = *(const float2*)&Rf[roff + col];
                    v0 += r.x; v1 += r.y;
                }
                if (C) *(float2*)&C[coff + col] = make_float2(v0, v1);
                if (Ch) {
                    float h0 = __bfloat162float(__float2bfloat16(v0));
                    float h1 = __bfloat162float(__float2bfloat16(v1));
                    st2bf(Ch, coff + col, v0, v1);
                    st2bf(Cm, coff + col, v0 - h0, v1 - h1);
                }
            }
        }
    }
}

// ------------- X: transpose+split (N-major) AND straight split (C-major) + row sums -------------
__global__ void tsplit2(const float* __restrict__ src)
{
    __shared__ float ts[32][33];
    int b = blockIdx.z;
    long o = (long)b * CIN * NN;
    int c0 = blockIdx.x * 32, r0 = blockIdx.y * 32;   // c0: n-dim, r0: channel
    int tx = threadIdx.x, ty = threadIdx.y;
#pragma unroll
    for (int i = 0; i < 4; i++) {
        int ch = r0 + ty + i * 8;
        long sidx = o + (long)ch * NN + c0 + tx;
        float v = src[sidx];
        ts[ty + i * 8][tx] = v;
        bf16 hh = __float2bfloat16(v);
        float r1 = v - __bfloat162float(hh);
        bf16 mm = __float2bfloat16(r1);
        g_Xch[sidx] = hh; g_Xcm[sidx] = mm;
        g_Xcl[sidx] = __float2bfloat16(r1 - __bfloat162float(mm));
        float sum = v;
#pragma unroll
        for (int off = 16; off; off >>= 1) sum += __shfl_xor_sync(0xffffffffu, sum, off);
        if (tx == 0) atomicAdd(&g_sx[b * CIN + ch], sum);
    }
    __syncthreads();
    // v = ts[tx][ty+i*8] = X[ch=r0+tx][n=c0+ty+i*8]; store at X_t[n][ch]
#pragma unroll
    for (int i = 0; i < 4; i++) {
        int n = c0 + ty + i * 8;
        float v = ts[tx][ty + i * 8];
        long tdx = (long)b * NN * CIN + (long)n * CIN + (r0 + tx);
        bf16 hh = __float2bfloat16(v);
        float r1 = v - __bfloat162float(hh);
        bf16 mm = __float2bfloat16(r1);
        g_Xh[tdx] = hh; g_Xm[tdx] = mm;
        g_Xl[tdx] = __float2bfloat16(r1 - __bfloat162float(mm));
    }
}

// ------------- all weight splits in one launch (incl. Wg transpose) -------------
__global__ void split_all(const float* __restrict__ Wt, const float* __restrict__ Wp,
                          const float* __restrict__ Wg, const float* __restrict__ W2,
                          const float* __restrict__ W3)
{
    int i = blockIdx.x * 256 + threadIdx.x;
    if (i < C1 * CIN) {
        float v = Wt[i];
        bf16 h = __float2bfloat16(v); float r1 = v - __bfloat162float(h);
        bf16 m = __float2bfloat16(r1);
        g_Wth[i] = h; g_Wtm[i] = m; g_Wtl[i] = __float2bfloat16(r1 - __bfloat162float(m));
        v = Wp[i];
        h = __float2bfloat16(v); r1 = v - __bfloat162float(h);
        m = __float2bfloat16(r1);
        g_Wph[i] = h; g_Wpm[i] = m; g_Wpl[i] = __float2bfloat16(r1 - __bfloat162float(m));
        // Wg: transpose into (k rows, d contig)
        v = Wg[i];
        int d = i >> 9, k = i & 511;      // Wg[d][k], row-major 256x512
        h = __float2bfloat16(v);
        g_WgTh[k * C1 + d] = h;
        g_WgTm[k * C1 + d] = __float2bfloat16(v - __bfloat162float(h));
        v = W2[i];
        h = __float2bfloat16(v);
        g_W2h[i] = h; g_W2m[i] = __float2bfloat16(v - __bfloat162float(h));
    }
    if (i < DD * CIN) {
        float v = W3[i];
        bf16 h = __float2bfloat16(v);
        g_W3h[i] = h; g_W3m[i] = __float2bfloat16(v - __bfloat162float(h));
    }
}

// ------------- reduce Gram split-K partials (lower-triangle mirror) + split -------------
__global__ void gram_reduce()
{
    long idx = (long)blockIdx.x * 256 + threadIdx.x;   // 8*512*512
    int b = (int)(idx >> 18);
    int rem = (int)(idx & 262143);
    int c1 = rem >> 9, c2 = rem & 511;
    long src = (c1 >> 7 >= c2 >> 7) ? ((long)c1 * 512 + c2) : ((long)c2 * 512 + c1);
    float v = 0.f;
#pragma unroll
    for (int s = 0; s < GS; s++) v += g_Gp[(((long)(b * GS + s)) << 18) + src];
    bf16 h = __float2bfloat16(v);
    float r1 = v - __bfloat162float(h);
    bf16 m = __float2bfloat16(r1);
    g_GRh[idx] = h; g_GRm[idx] = m;
    g_GRl[idx] = __float2bfloat16(r1 - __bfloat162float(m));
}

// ------------- reduce T1 split-K partials + 3-way split -------------
__global__ void t1_reduce()
{
    long idx = (long)blockIdx.x * 256 + threadIdx.x;   // 8*131072
    int b = (int)(idx >> 17);
    long il = idx & 131071;
    float v = 0.f;
#pragma unroll
    for (int s = 0; s < 4; s++) v += g_T1p[(((long)(b * 4 + s)) << 17) + il];
    bf16 h = __float2bfloat16(v);
    float r1 = v - __bfloat162float(h);
    bf16 m = __float2bfloat16(r1);
    g_T1h[idx] = h; g_T1m[idx] = m;
    g_T1l[idx] = __float2bfloat16(r1 - __bfloat162float(m));
}

// ------------- M transpose/split (both orientations) -------------
__global__ void msplit()
{
    long idx = (long)blockIdx.x * 256 + threadIdx.x;   // 8*512*512
    int b = (int)(idx >> 18);
    int rem = (int)(idx & 262143);
    int k = rem >> 9, cc = rem & 511;
    float v = g_Mf[idx];
    bf16 h = __float2bfloat16(v);
    bf16 m = __float2bfloat16(v - __bfloat162float(h));
    g_Mkh[idx] = h; g_Mkm[idx] = m;                     // (k rows, cc contig)
    long tdx = (((long)b) << 18) + ((long)cc << 9) + k; // (cc rows, k contig)
    g_Mch[tdx] = h; g_Mcm[tdx] = m;
}

// ------------- bias rank-1 corrections: bth = Wtheta*sx, bph = Wphi*sx -------------
__global__ void bcorr(const float* __restrict__ Wt, const float* __restrict__ Wp)
{
    int idx = blockIdx.x * 256 + threadIdx.x;   // 2*8*256
    int which = idx >> 11;
    int r = idx & 2047;
    int b = r >> 8, c = r & 255;
    const float* W = which ? Wp : Wt;
    float s = 0.f;
    for (int k = 0; k < CIN; k++) s += W[c * CIN + k] * g_sx[b * CIN + k];
    (which ? g_bph : g_bth)[b * C1 + c] = s;
}

// ------------- b2e = b2 + Wf·bg  (per batch) -------------
__global__ void b2e_kernel(const float* __restrict__ b2, const float* __restrict__ bg)
{
    int idx = blockIdx.x * 256 + threadIdx.x;   // 8*512
    int b = idx >> 9, c = idx & 511;
    float s = b2[c];
    long base = ((long)b << 17) + (long)c * C1;
    for (int d = 0; d < C1; d++)
        s += bg[d] * (__bfloat162float(g_Wfh[base + d]) + __bfloat162float(g_Wfm[base + d]));
    g_b2e[idx] = s;
}

// ------------- b3e = W3·b2e + b3  (per batch) -------------
__global__ void b3e_kernel(const float* __restrict__ W3, const float* __restrict__ b3)
{
    int idx = blockIdx.x * 256 + threadIdx.x;   // 8*128
    int b = idx >> 7, d = idx & 127;
    float s = b3[d];
    for (int c = 0; c < CIN; c++) s += g_b2e[b * CIN + c] * W3[d * CIN + c];
    g_b3e[idx] = s;
}

// ------------- softmax over f rows (sum split-K partials + bias corr), f^T bf16 out -------------
__global__ void softmaxT(const float* __restrict__ bth_bias, const float* __restrict__ bph_bias)
{
    int row = blockIdx.x, t = threadIdx.x;
    int b = row >> 8, c = row & 255;
    long il = (long)c * 256 + t;
    float v = 0.f;
#pragma unroll
    for (int s = 0; s < 4; s++) v += g_Fp4[(((long)(b * 4 + s)) << 16) + il];
    v += bth_bias[c] * g_bph[b * C1 + t]
       + bph_bias[t] * g_bth[b * C1 + c]
       + (float)NN * bth_bias[c] * bph_bias[t];
    __shared__ float sh[256];
    sh[t] = v; __syncthreads();
    for (int o = 128; o; o >>= 1) { if (t < o) sh[t] = fmaxf(sh[t], sh[t + o]); __syncthreads(); }
    float mx = sh[0]; __syncthreads();
    float e = expf(v - mx);
    sh[t] = e; __syncthreads();
    for (int o = 128; o; o >>= 1) { if (t < o) sh[t] += sh[t + o]; __syncthreads(); }
    float r = e / sh[0];
    long o2 = ((long)b << 16) + (long)t * 256 + c;   // f^T[d=t, c]
    bf16 h = __float2bfloat16(r);
    g_Fh[o2] = h;
    g_Fm[o2] = __float2bfloat16(r - __bfloat162float(h));
}

// ------------- zero accumulators -------------
__global__ void zero_kernel() {
    int i = blockIdx.x * blockDim.x + threadIdx.x;
    if (i < BB * KK * DD) g_Eacc[i] = 0.f;
    if (i < BB * KK)      g_Asum[i] = 0.f;
    if (i < BB * DD)      g_Es[i]   = 0.f;
    if (i < BB * CIN)     g_sx[i]   = 0.f;
}

// ------------- fused dist -> softmax(A) -> E accumulation -------------
__global__ __launch_bounds__(256) void encode_kernel(
    const float* __restrict__ ZDt,
    const float* __restrict__ codewords, const float* __restrict__ scale,
    float* __restrict__ Eacc, float* __restrict__ Asum)
{
    int b = blockIdx.y;
    __shared__ float cs[KK][DD + 1];
    __shared__ float cn[KK], sc[KK];
    __shared__ float xs[DD][33];
    __shared__ float Ash[8][KK];
    int tid = threadIdx.x, lane = tid & 31, wid = tid >> 5;

    for (int i = tid; i < KK * DD; i += 256) cs[i >> 7][i & 127] = codewords[i];
    if (tid < KK) sc[tid] = scale[tid];
    __syncthreads();
    if (tid < KK) {
        float s = 0.f;
        for (int d = 0; d < DD; d++) { float c = cs[tid][d]; s += c * c; }
        cn[tid] = s;
    }
    __syncthreads();

    float ereg[16];
#pragma unroll
    for (int i = 0; i < 16; i++) ereg[i] = 0.f;
    float asum_local = 0.f;
    int myk = tid >> 3, myd0 = tid & 7;

    for (int t = blockIdx.x; t < NN / 32; t += gridDim.x) {
        int n0 = t * 32;
#pragma unroll
        for (int r = 0; r < 4; r++) {
            int idx = r * 256 + tid;
            int n = idx >> 5, d4 = (idx & 31) * 4;
            float4 v = *(const float4*)(ZDt + ((long)b * NN + n0 + n) * DD + d4);
            xs[d4][n] = v.x; xs[d4 + 1][n] = v.y; xs[d4 + 2][n] = v.z; xs[d4 + 3][n] = v.w;
        }
        __syncthreads();
        for (int round = 0; round < 4; round++) {
            int n = round * 8 + wid;
            float xx = 0.f;
            for (int d = lane; d < DD; d += 32) { float x = xs[d][n]; xx += x * x; }
            for (int o = 16; o; o >>= 1) xx += __shfl_xor_sync(0xffffffffu, xx, o);
            float dot = 0.f;
#pragma unroll 8
            for (int d = 0; d < DD; d++) dot += xs[d][n] * cs[lane][d];
            float s = sc[lane] * (xx - 2.f * dot + cn[lane]);
            float mx = s;
            for (int o = 16; o; o >>= 1) mx = fmaxf(mx, __shfl_xor_sync(0xffffffffu, mx, o));
            float e = __expf(s - mx);
            float ssum = e;
            for (int o = 16; o; o >>= 1) ssum += __shfl_xor_sync(0xffffffffu, ssum, o);
            float a = e / ssum;
            Ash[wid][lane] = a;
            asum_local += a;
            __syncthreads();
#pragma unroll
            for (int nn2 = 0; nn2 < 8; nn2++) {
                float av = Ash[nn2][myk];
                int ncol = round * 8 + nn2;
#pragma unroll
                for (int i = 0; i < 16; i++)
                    ereg[i] += av * xs[myd0 + 8 * i][ncol];
            }
            __syncthreads();
        }
    }
#pragma unroll
    for (int i = 0; i < 16; i++)
        atomicAdd(&Eacc[((long)b * KK + myk) * DD + myd0 + 8 * i], ereg[i]);
    atomicAdd(&Asum[b * KK + lane], asum_local);
}

// ------------- BN over K + Es -------------
__global__ void bn_es_kernel(const float* __restrict__ Eacc, const float* __restrict__ Asum,
                             const float* __restrict__ codewords, float* __restrict__ Es)
{
    int k = blockIdx.x, tid = threadIdx.x;
    __shared__ double shs[256], shs2[256];
    float vals[4];
    double s = 0.0, s2 = 0.0;
#pragma unroll
    for (int i = 0; i < 4; i++) {
        int idx = tid + i * 256;
        int b = idx >> 7, d = idx & 127;
        float v = Eacc[((long)b * KK + k) * DD + d] - Asum[b * KK + k] * codewords[k * DD + d];
        vals[i] = v; s += v; s2 += (double)v * v;
    }
    shs[tid] = s; shs2[tid] = s2; __syncthreads();
    for (int o = 128; o; o >>= 1) {
        if (tid < o) { shs[tid] += shs[tid + o]; shs2[tid] += shs2[tid + o]; }
        __syncthreads();
    }
    double mean = shs[0] / 1024.0;
    double var = shs2[0] / 1024.0 - mean * mean;
    float inv = rsqrtf((float)var + 1e-5f);
    float mf = (float)mean;
#pragma unroll
    for (int i = 0; i < 4; i++) {
        int idx = tid + i * 256;
        int b = idx >> 7, d = idx & 127;
        float e = (vals[i] - mf) * inv;
        if (e > 0.f) atomicAdd(&Es[b * DD + d], e);
    }
}

// ------------- gamma = sigmoid(Es @ W_fc^T + b_fc) -------------
__global__ void gamma_kernel(const float* __restrict__ Es, const float* __restrict__ W_fc,
                             const float* __restrict__ b_fc, float* __restrict__ gam)
{
    int idx = blockIdx.x * blockDim.x + threadIdx.x;
    int b = idx / CIN, c = idx % CIN;
    float s = b_fc[c];
    for (int d = 0; d < DD; d++) s += Es[b * DD + d] * W_fc[c * DD + d];
    gam[idx] = 1.f / (1.f + expf(-s));
}

// ------------- out = Zct * gamma (elementwise; Zct already (B,C,N)) -------------
__global__ void scale_out(const float* __restrict__ Zct, const float* __restrict__ gam,
                          float* __restrict__ out)
{
    long idx4 = (long)blockIdx.x * 256 + threadIdx.x;
    const long total4 = (long)BB * CIN * NN / 4;
    if (idx4 >= total4) return;
    long elem = idx4 * 4;
    int bc = (int)(elem / NN);           // b*CIN + c
    float g = gam[bc];
    float4 v = ((const float4*)Zct)[idx4];
    v.x *= g; v.y *= g; v.z *= g; v.w *= g;
    ((float4*)out)[idx4] = v;
}

// ------------- launch -------------
#define GA(T, p, s) T* p; cudaGetSymbolAddress((void**)&p, s)

extern "C" void kernel_launch(void* const* d_in, const int* in_sizes, int n_in,
                              void* d_out, int out_size)
{
    const float* X        = (const float*)d_in[0];
    const float* W_theta  = (const float*)d_in[1];
    const float* b_theta  = (const float*)d_in[2];
    const float* W_phi    = (const float*)d_in[3];
    const float* b_phi    = (const float*)d_in[4];
    const float* W_g      = (const float*)d_in[5];
    const float* b_g      = (const float*)d_in[6];
    const float* W2       = (const float*)d_in[7];
    const float* b2       = (const float*)d_in[8];
    const float* W3       = (const float*)d_in[9];
    const float* b3       = (const float*)d_in[10];
    const float* codewords= (const float*)d_in[11];
    const float* scale    = (const float*)d_in[12];
    const float* W_fc     = (const float*)d_in[13];
    const float* b_fc     = (const float*)d_in[14];

    GA(bf16, Xh, g_Xh); GA(bf16, Xm, g_Xm);
    GA(bf16, Xch, g_Xch); GA(bf16, Xcm, g_Xcm); GA(bf16, Xcl, g_Xcl);
    GA(bf16, Wth, g_Wth); GA(bf16, Wtm, g_Wtm); GA(bf16, Wtl, g_Wtl);
    GA(bf16, Wph, g_Wph); GA(bf16, Wpm, g_Wpm); GA(bf16, Wpl, g_Wpl);
    GA(bf16, WgTh, g_WgTh); GA(bf16, WgTm, g_WgTm);
    GA(bf16, W2h, g_W2h); GA(bf16, W2m, g_W2m);
    GA(bf16, W3h, g_W3h); GA(bf16, W3m, g_W3m);
    GA(float, Gp, g_Gp);
    GA(bf16, GRh, g_GRh); GA(bf16, GRm, g_GRm); GA(bf16, GRl, g_GRl);
    GA(float, T1p, g_T1p);
    GA(bf16, T1h, g_T1h); GA(bf16, T1m, g_T1m); GA(bf16, T1l, g_T1l);
    GA(float, Fp4, g_Fp4);
    GA(bf16, Fh, g_Fh); GA(bf16, Fm, g_Fm);
    GA(bf16, Wfh, g_Wfh); GA(bf16, Wfm, g_Wfm);
    GA(float, Mf, g_Mf);
    GA(bf16, Mkh, g_Mkh); GA(bf16, Mkm, g_Mkm);
    GA(bf16, Mch, g_Mch); GA(bf16, Mcm, g_Mcm);
    GA(bf16, M2h, g_M2h); GA(bf16, M2m, g_M2m);
    GA(float, b2e, g_b2e); GA(float, b3e, g_b3e);
    GA(float, Zct, g_Zct); GA(float, ZDt, g_ZDt);
    GA(float, Eacc, g_Eacc); GA(float, Asum, g_Asum);
    GA(float, Es, g_Es); GA(float, gamB, g_gam);

    const int SM6 = 2 * 6 * 8192;   // 98304
    const int SM3 = 2 * 4 * 8192;   // 65536
    cudaFuncSetAttribute((const void*)mma_gemm<6, false>, cudaFuncAttributeMaxDynamicSharedMemorySize, SM6);
    cudaFuncSetAttribute((const void*)mma_gemm<6, true>,  cudaFuncAttributeMaxDynamicSharedMemorySize, SM6);
    cudaFuncSetAttribute((const void*)mma_gemm<3, false>, cudaFuncAttributeMaxDynamicSharedMemorySize, SM3);

    zero_kernel<<<128, 256>>>();
    tsplit2<<<dim3(288, 16, BB), dim3(32, 8)>>>(X);
    split_all<<<512, 256>>>(W_theta, W_phi, W_g, W2, W3);

    // Gram: G = X·X^T per batch, lower-triangle tiles, split-K=18 (KS=512)
    mma_gemm<6, true><<<dim3(10, 1, BB * GS), 256, SM6>>>(
        Xch, Xcm, Xcl, NN, (long)CIN * NN, Xch, Xcm, Xcl, NN, (long)CIN * NN,
        Gp, nullptr, nullptr, CIN, (long)CIN * CIN,
        nullptr, 0, nullptr, 0, nullptr, 0, 16, GS);
    gram_reduce<<<8192, 256>>>();

    // T1 = Wphi @ G (256x512/batch), x6, split-K=4 -> fp32 partials
    mma_gemm<6, false><<<dim3(4, 2, BB * 4), 256, SM6>>>(
        Wph, Wpm, Wpl, CIN, 0, GRh, GRm, GRl, CIN, (long)CIN * CIN,
        T1p, nullptr, nullptr, CIN, 131072L,
        nullptr, 0, nullptr, 0, nullptr, 0, 4, 4);
    t1_reduce<<<4096, 256>>>();

    // f = Wtheta @ T1^T (256x256/batch), x6, split-K=4 -> fp32 partials
    mma_gemm<6, false><<<dim3(2, 2, BB * 4), 256, SM6>>>(
        Wth, Wtm, Wtl, CIN, 0, T1h, T1m, T1l, CIN, 131072L,
        Fp4, nullptr, nullptr, C1, 65536L,
        nullptr, 0, nullptr, 0, nullptr, 0, 4, 4);

    bcorr<<<16, 256>>>(W_theta, W_phi);
    softmaxT<<<BB * C1, 256>>>(b_theta, b_phi);

    // Wf = W2 @ f^T: (512 x 256)/batch, x3 -> h/m parts
    mma_gemm<3, false><<<dim3(2, 4, BB), 256, SM3>>>(
        W2h, W2m, nullptr, C1, 0, Fh, Fm, nullptr, C1, 65536L,
        nullptr, Wfh, Wfm, C1, 131072L,
        nullptr, 0, nullptr, 0, nullptr, 0, 8, 1);

    b2e_kernel<<<16, 256>>>(b2, b_g);
    b3e_kernel<<<4, 256>>>(W3, b3);

    // M[k,cc] = Wg^T · Wf^T : A=WgT (k,d), B=Wf (cc,d), K=256, fp32 out
    mma_gemm<3, false><<<dim3(4, 4, BB), 256, SM3>>>(
        WgTh, WgTm, nullptr, C1, 0, Wfh, Wfm, nullptr, C1, 131072L,
        Mf, nullptr, nullptr, CIN, 262144L,
        nullptr, 0, nullptr, 0, nullptr, 0, 8, 1);
    msplit<<<8192, 256>>>();

    // M2^T[d,k] = W3 · Mk + W3 (residual): A=W3 (d,c), B=Mk (k,c), K=512 -> h/m parts
    mma_gemm<3, false><<<dim3(4, 1, BB), 256, SM3>>>(
        W3h, W3m, nullptr, CIN, 0, Mkh, Mkm, nullptr, CIN, 262144L,
        nullptr, M2h, M2m, CIN, 65536L,
        nullptr, 0, nullptr, 0, W3, 0, 16, 1);

    // z (B,C,N): C[cc,n] = Mc·X_t^T + b2e[cc] + X : A=Mc (cc,k), B=X_t (n,k), K=512
    mma_gemm<3, false><<<dim3(72, 4, BB), 256, SM3>>>(
        Mch, Mcm, nullptr, CIN, 262144L, Xh, Xm, nullptr, CIN, (long)NN * CIN,
        Zct, nullptr, nullptr, NN, (long)CIN * NN,
        nullptr, 0, b2e, CIN, X, (long)CIN * NN, 16, 1);

    // z_ (n rows, d contig): C[n,d] = X_t·M2 + b3e[d] : A=X_t (n,k), B=M2^T (d,k), K=512
    mma_gemm<3, false><<<dim3(1, 72, BB), 256, SM3>>>(
        Xh, Xm, nullptr, CIN, (long)NN * CIN, M2h, M2m, nullptr, CIN, 65536L,
        ZDt, nullptr, nullptr, DD, (long)NN * DD,
        b3e, DD, nullptr, 0, nullptr, 0, 16, 1);

    encode_kernel<<<dim3(96, BB), 256>>>(ZDt, codewords, scale, Eacc, Asum);
    bn_es_kernel<<<KK, 256>>>(Eacc, Asum, codewords, Es);
    gamma_kernel<<<(BB * CIN) / 256, 256>>>(Es, W_fc, b_fc, gamB);
    scale_out<<<36864, 256>>>(Zct, gamB, (float*)d_out);
}

// round 12
// speedup vs baseline: 1.0375x; 1.0375x over previous
#include <cuda_runtime.h>
#include <cuda_bf16.h>
#include <math.h>
#include <stdint.h>

#define BB 8
#define CIN 512
#define C1 256
#define DD 128
#define KK 32
#define NN 9216
#define ROWS (BB*NN)
#define GS 18            // Gram split-K slices
typedef __nv_bfloat16 bf16;
typedef unsigned int u32;

// ------------- scratch (device globals) -------------
__device__ bf16 g_Xh[ROWS*CIN], g_Xm[ROWS*CIN];                      // X (N-major rows n, k contig)
__device__ bf16 g_Xch[ROWS*CIN], g_Xcm[ROWS*CIN], g_Xcl[ROWS*CIN];   // X (C-major rows ch, n contig)
__device__ bf16 g_Wth[C1*CIN], g_Wtm[C1*CIN], g_Wtl[C1*CIN];
__device__ bf16 g_Wph[C1*CIN], g_Wpm[C1*CIN], g_Wpl[C1*CIN];
__device__ bf16 g_WgTh[CIN*C1], g_WgTm[CIN*C1];                      // Wg^T (k rows, d contig)
__device__ bf16 g_W2h[CIN*C1], g_W2m[CIN*C1];
__device__ bf16 g_W3h[DD*CIN], g_W3m[DD*CIN];
__device__ float g_Gp[(BB*GS)*CIN*CIN];                              // Gram split-K partials
__device__ bf16 g_GRh[BB*CIN*CIN], g_GRm[BB*CIN*CIN], g_GRl[BB*CIN*CIN];
__device__ float g_T1p[BB*4*C1*CIN];                                 // T1 split-K partials
__device__ bf16 g_T1h[BB*C1*CIN], g_T1m[BB*C1*CIN], g_T1l[BB*C1*CIN];
__device__ float g_Fp4[BB*4*C1*C1];                                  // f split-K partials
__device__ bf16 g_Fh[BB*C1*C1], g_Fm[BB*C1*C1];                      // f^T parts (d rows, c contig)
__device__ bf16 g_Wfh[BB*CIN*C1], g_Wfm[BB*CIN*C1];                  // Wf = W2·f (cc rows, d contig)
__device__ float g_Mf[BB*CIN*CIN];                                   // M fp32 (k rows, cc contig)
__device__ bf16 g_Mkh[BB*CIN*CIN], g_Mkm[BB*CIN*CIN];                // M (k rows, cc contig)
__device__ bf16 g_Mch[BB*CIN*CIN], g_Mcm[BB*CIN*CIN];                // (M+I)^T (cc rows, k contig)
__device__ bf16 g_M2h[BB*DD*CIN], g_M2m[BB*DD*CIN];                  // M2^T (d rows, k contig)
__device__ float g_b2e[BB*CIN];                                      // b2 + Wf·bg
__device__ float g_b3e[BB*DD];                                       // W3·b2e + b3
__device__ float g_ZDt[ROWS*DD];                                     // z_ rows n, d contig
__device__ float g_sx[BB*CIN];
__device__ float g_bth[BB*C1], g_bph[BB*C1];
__device__ float g_Eacc[BB*KK*DD], g_Asum[BB*KK], g_Es[BB*DD], g_gam[BB*CIN];

// ------------- helpers -------------
__device__ __forceinline__ u32 smem_u32(const void* p) {
    u32 a;
    asm("{ .reg .u64 t; cvta.to.shared.u64 t, %1; cvt.u32.u64 %0, t; }" : "=r"(a) : "l"(p));
    return a;
}
__device__ __forceinline__ void cp16(u32 d, const void* s) {
    asm volatile("cp.async.cg.shared.global [%0], [%1], 16;" :: "r"(d), "l"(s));
}
__device__ __forceinline__ void cp_commit() { asm volatile("cp.async.commit_group;" ::: "memory"); }
template<int N> __device__ __forceinline__ void cp_waitg() {
    asm volatile("cp.async.wait_group %0;" :: "n"(N) : "memory");
}
__device__ __forceinline__ void ldm_x4(u32* r, u32 addr) {
    asm volatile("ldmatrix.sync.aligned.m8n8.x4.shared.b16 {%0,%1,%2,%3}, [%4];"
        : "=r"(r[0]), "=r"(r[1]), "=r"(r[2]), "=r"(r[3]) : "r"(addr));
}
__device__ __forceinline__ void mma16816(float* d, const u32* a, const u32* b) {
    asm volatile(
        "mma.sync.aligned.m16n8k16.row.col.f32.bf16.bf16.f32 "
        "{%0,%1,%2,%3}, {%4,%5,%6,%7}, {%8,%9}, {%0,%1,%2,%3};"
        : "+f"(d[0]), "+f"(d[1]), "+f"(d[2]), "+f"(d[3])
        : "r"(a[0]), "r"(a[1]), "r"(a[2]), "r"(a[3]), "r"(b[0]), "r"(b[1]));
}
__device__ __forceinline__ void st2bf(bf16* p, long i, float a, float b_) {
    __nv_bfloat162 v(__float2bfloat16(a), __float2bfloat16(b_));
    *(u32*)(p + i) = *(u32*)&v;
}

// ============ mma.sync bf16-split GEMM, product-shared tiles, BK=32 ============
// C[z; m, n] = sum over triangular products A_pa * B_pb (pa+pb<NB), K-major.
// SYM: blockIdx.x indexes lower-triangle 128x128 tile pairs of a 512x512 output.
// out = ((acc + biasR[row] + biasC[col] + Rf[row,col]) * scaleR[row])
template<int NPROD, bool SYM>
__global__ __launch_bounds__(256, 2) void mma_gemm(
    const bf16* __restrict__ Ah, const bf16* __restrict__ Am, const bf16* __restrict__ Al,
    int lda, long sAb,
    const bf16* __restrict__ Bh, const bf16* __restrict__ Bm, const bf16* __restrict__ Bl,
    int ldb, long sBb,
    float* __restrict__ C, bf16* __restrict__ Ch, bf16* __restrict__ Cm,
    int ldc, long sCz,
    const float* __restrict__ biasC, long sBC,
    const float* __restrict__ biasR, long sBR,
    const float* __restrict__ Rf, long sRz,
    const float* __restrict__ scaleR, long sSR,
    int NCH, int S)
{
    constexpr int NA = (NPROD == 6) ? 3 : 2;
    constexpr int NB = NA;
    constexpr int STAGE = (NA + NB) * 8192;

    extern __shared__ __align__(16) char smem[];
    const u32 sbase = smem_u32(smem);

    const int tid = threadIdx.x, lane = tid & 31, wid = tid >> 5;
    const int wm = wid & 1, wn = wid >> 1;
    const int z = blockIdx.z, b = z / S, s = z % S;
    int bx, by;
    if (SYM) {
        int p = blockIdx.x;
        by = (p < 1) ? 0 : (p < 3) ? 1 : (p < 6) ? 2 : 3;
        bx = p - (by * (by + 1)) / 2;
    } else { bx = blockIdx.x; by = blockIdx.y; }
    const long m0 = (long)by * 128;
    const int n0 = bx * 128;
    const int KS = NCH * 32;

    const long abase = (long)b * sAb + m0 * lda + (long)s * KS;
    const long bbase = (long)b * sBb + (long)n0 * ldb + (long)s * KS;

    const bf16* APT[3] = {Ah, Am, Al};
    const bf16* BPT[3] = {Bh, Bm, Bl};

    float acc[4][4][4];
#pragma unroll
    for (int i = 0; i < 4; i++)
#pragma unroll
        for (int j = 0; j < 4; j++)
#pragma unroll
            for (int r = 0; r < 4; r++) acc[i][j][r] = 0.f;

    const int row2 = tid >> 1, lq = tid & 1;
    const int sw = (row2 >> 1) & 3;
    const u32 c0off = (u32)(row2 * 64 + (((lq * 2 + 0) ^ sw) << 4));
    const u32 c1off = (u32)(row2 * 64 + (((lq * 2 + 1) ^ sw) << 4));

    auto issue = [&](int c) {
        int k0 = c * 32;
        u32 sd = sbase + (c & 1) * STAGE;
#pragma unroll
        for (int p = 0; p < NA; p++) {
            const bf16* ap = APT[p] + abase + k0 + (long)row2 * lda + lq * 16;
            cp16(sd + p * 8192 + c0off, ap);
            cp16(sd + p * 8192 + c1off, ap + 8);
        }
#pragma unroll
        for (int p = 0; p < NB; p++) {
            const bf16* bp = BPT[p] + bbase + k0 + (long)row2 * ldb + lq * 16;
            cp16(sd + (NA + p) * 8192 + c0off, bp);
            cp16(sd + (NA + p) * 8192 + c1off, bp + 8);
        }
        cp_commit();
    };

    u32 aoff[4], boff[2];
#pragma unroll
    for (int t = 0; t < 4; t++) {
        int ra = wm * 64 + t * 16 + (lane & 15);
        int j = lane >> 4;
        aoff[t] = (u32)(ra * 64 + ((j ^ ((ra >> 1) & 3)) << 4));
    }
#pragma unroll
    for (int u = 0; u < 2; u++) {
        int rb = wn * 32 + u * 16 + (lane & 7) + ((lane >> 4) & 1) * 8;
        int j = (lane >> 3) & 1;
        boff[u] = (u32)(rb * 64 + ((j ^ ((rb >> 1) & 3)) << 4));
    }

    issue(0);
    for (int c = 0; c < NCH; c++) {
        if (c + 1 < NCH) { issue(c + 1); cp_waitg<1>(); }
        else cp_waitg<0>();
        __syncthreads();
        u32 sA = sbase + (c & 1) * STAGE;
        u32 sB = sA + NA * 8192;
#pragma unroll
        for (int kk = 0; kk < 2; kk++) {
            u32 kx = kk << 5;
            u32 bfr[NB][2][4];
#pragma unroll
            for (int pb = 0; pb < NB; pb++)
#pragma unroll
                for (int u = 0; u < 2; u++)
                    ldm_x4(bfr[pb][u], sB + pb * 8192 + (boff[u] ^ kx));
#pragma unroll
            for (int pa = 0; pa < NA; pa++) {
                u32 af[4][4];
#pragma unroll
                for (int t = 0; t < 4; t++)
                    ldm_x4(af[t], sA + pa * 8192 + (aoff[t] ^ kx));
#pragma unroll
                for (int pb = 0; pb < NB; pb++) {
                    if (pa + pb < NB) {
#pragma unroll
                        for (int mi = 0; mi < 4; mi++)
#pragma unroll
                            for (int ni = 0; ni < 4; ni++)
                                mma16816(acc[mi][ni], af[mi], &bfr[pb][ni >> 1][(ni & 1) * 2]);
                    }
                }
            }
        }
        __syncthreads();
    }

    // ---- epilogue ----
    const int mrow = lane >> 2, nc2 = (lane & 3) * 2;
#pragma unroll
    for (int mi = 0; mi < 4; mi++) {
#pragma unroll
        for (int rp = 0; rp < 2; rp++) {
            long row = m0 + wm * 64 + mi * 16 + mrow + rp * 8;
            long coff = (long)z * sCz + row * ldc;
            long roff = (long)b * sRz + row * ldc;
            float br = biasR ? biasR[b * sBR + row] : 0.f;
            float sr = scaleR ? scaleR[b * sSR + row] : 1.f;
#pragma unroll
            for (int ni = 0; ni < 4; ni++) {
                int col = n0 + wn * 32 + ni * 8 + nc2;
                float v0 = acc[mi][ni][rp * 2 + 0] + br;
                float v1 = acc[mi][ni][rp * 2 + 1] + br;
                if (biasC) { v0 += biasC[b * sBC + col]; v1 += biasC[b * sBC + col + 1]; }
                if (Rf) {
                    float2 r = *(const float2*)&Rf[roff + col];
                    v0 += r.x; v1 += r.y;
                }
                v0 *= sr; v1 *= sr;
                if (C) *(float2*)&C[coff + col] = make_float2(v0, v1);
                if (Ch) {
                    float h0 = __bfloat162float(__float2bfloat16(v0));
                    float h1 = __bfloat162float(__float2bfloat16(v1));
                    st2bf(Ch, coff + col, v0, v1);
                    st2bf(Cm, coff + col, v0 - h0, v1 - h1);
                }
            }
        }
    }
}

// ------------- X: transpose+split (N-major h/m) AND straight split (C-major h/m/l) + row sums -------------
__global__ void tsplit2(const float* __restrict__ src)
{
    __shared__ float ts[32][33];
    int b = blockIdx.z;
    long o = (long)b * CIN * NN;
    int c0 = blockIdx.x * 32, r0 = blockIdx.y * 32;   // c0: n-dim, r0: channel
    int tx = threadIdx.x, ty = threadIdx.y;
#pragma unroll
    for (int i = 0; i < 4; i++) {
        int ch = r0 + ty + i * 8;
        long sidx = o + (long)ch * NN + c0 + tx;
        float v = src[sidx];
        ts[ty + i * 8][tx] = v;
        bf16 hh = __float2bfloat16(v);
        float r1 = v - __bfloat162float(hh);
        bf16 mm = __float2bfloat16(r1);
        g_Xch[sidx] = hh; g_Xcm[sidx] = mm;
        g_Xcl[sidx] = __float2bfloat16(r1 - __bfloat162float(mm));
        float sum = v;
#pragma unroll
        for (int off = 16; off; off >>= 1) sum += __shfl_xor_sync(0xffffffffu, sum, off);
        if (tx == 0) atomicAdd(&g_sx[b * CIN + ch], sum);
    }
    __syncthreads();
    // v = ts[tx][ty+i*8] = X[ch=r0+tx][n=c0+ty+i*8]; store at X_t[n][ch]
#pragma unroll
    for (int i = 0; i < 4; i++) {
        int n = c0 + ty + i * 8;
        float v = ts[tx][ty + i * 8];
        long tdx = (long)b * NN * CIN + (long)n * CIN + (r0 + tx);
        bf16 hh = __float2bfloat16(v);
        g_Xh[tdx] = hh;
        g_Xm[tdx] = __float2bfloat16(v - __bfloat162float(hh));
    }
}

// ------------- weight splits + accumulator zeroing (one launch; runs FIRST) -------------
__global__ void split_all(const float* __restrict__ Wt, const float* __restrict__ Wp,
                          const float* __restrict__ Wg, const float* __restrict__ W2,
                          const float* __restrict__ W3)
{
    int i = blockIdx.x * 256 + threadIdx.x;
    if (i < BB * KK * DD) g_Eacc[i] = 0.f;
    if (i < BB * KK)      g_Asum[i] = 0.f;
    if (i < BB * DD)      g_Es[i]   = 0.f;
    if (i < BB * CIN)     g_sx[i]   = 0.f;
    if (i < C1 * CIN) {
        float v = Wt[i];
        bf16 h = __float2bfloat16(v); float r1 = v - __bfloat162float(h);
        bf16 m = __float2bfloat16(r1);
        g_Wth[i] = h; g_Wtm[i] = m; g_Wtl[i] = __float2bfloat16(r1 - __bfloat162float(m));
        v = Wp[i];
        h = __float2bfloat16(v); r1 = v - __bfloat162float(h);
        m = __float2bfloat16(r1);
        g_Wph[i] = h; g_Wpm[i] = m; g_Wpl[i] = __float2bfloat16(r1 - __bfloat162float(m));
        // Wg: transpose into (k rows, d contig)
        v = Wg[i];
        int d = i >> 9, k = i & 511;      // Wg[d][k], row-major 256x512
        h = __float2bfloat16(v);
        g_WgTh[k * C1 + d] = h;
        g_WgTm[k * C1 + d] = __float2bfloat16(v - __bfloat162float(h));
        v = W2[i];
        h = __float2bfloat16(v);
        g_W2h[i] = h; g_W2m[i] = __float2bfloat16(v - __bfloat162float(h));
    }
    if (i < DD * CIN) {
        float v = W3[i];
        bf16 h = __float2bfloat16(v);
        g_W3h[i] = h; g_W3m[i] = __float2bfloat16(v - __bfloat162float(h));
    }
}

// ------------- reduce Gram split-K partials (lower-triangle mirror) + split -------------
__global__ void gram_reduce()
{
    long idx = (long)blockIdx.x * 256 + threadIdx.x;   // 8*512*512
    int b = (int)(idx >> 18);
    int rem = (int)(idx & 262143);
    int c1 = rem >> 9, c2 = rem & 511;
    long src = (c1 >> 7 >= c2 >> 7) ? ((long)c1 * 512 + c2) : ((long)c2 * 512 + c1);
    float v = 0.f;
#pragma unroll
    for (int s = 0; s < GS; s++) v += g_Gp[(((long)(b * GS + s)) << 18) + src];
    bf16 h = __float2bfloat16(v);
    float r1 = v - __bfloat162float(h);
    bf16 m = __float2bfloat16(r1);
    g_GRh[idx] = h; g_GRm[idx] = m;
    g_GRl[idx] = __float2bfloat16(r1 - __bfloat162float(m));
}

// ------------- reduce T1 split-K partials + 3-way split -------------
__global__ void t1_reduce()
{
    long idx = (long)blockIdx.x * 256 + threadIdx.x;   // 8*131072
    int b = (int)(idx >> 17);
    long il = idx & 131071;
    float v = 0.f;
#pragma unroll
    for (int s = 0; s < 4; s++) v += g_T1p[(((long)(b * 4 + s)) << 17) + il];
    bf16 h = __float2bfloat16(v);
    float r1 = v - __bfloat162float(h);
    bf16 m = __float2bfloat16(r1);
    g_T1h[idx] = h; g_T1m[idx] = m;
    g_T1l[idx] = __float2bfloat16(r1 - __bfloat162float(m));
}

// ------------- M split: Mk = M (k rows), Mc = (M+I)^T (cc rows) -------------
__global__ void msplit()
{
    long idx = (long)blockIdx.x * 256 + threadIdx.x;   // 8*512*512
    int b = (int)(idx >> 18);
    int rem = (int)(idx & 262143);
    int k = rem >> 9, cc = rem & 511;
    float v = g_Mf[idx];
    bf16 h = __float2bfloat16(v);
    bf16 m = __float2bfloat16(v - __bfloat162float(h));
    g_Mkh[idx] = h; g_Mkm[idx] = m;                     // M (k rows, cc contig), no I
    float v2 = v + (k == cc ? 1.f : 0.f);               // fold +X residual into M
    bf16 h2 = __float2bfloat16(v2);
    bf16 m2 = __float2bfloat16(v2 - __bfloat162float(h2));
    long tdx = (((long)b) << 18) + ((long)cc << 9) + k; // (cc rows, k contig)
    g_Mch[tdx] = h2; g_Mcm[tdx] = m2;
}

// ------------- bias rank-1 corrections: bth = Wtheta*sx, bph = Wphi*sx -------------
__global__ void bcorr(const float* __restrict__ Wt, const float* __restrict__ Wp)
{
    int idx = blockIdx.x * 256 + threadIdx.x;   // 2*8*256
    int which = idx >> 11;
    int r = idx & 2047;
    int b = r >> 8, c = r & 255;
    const float* W = which ? Wp : Wt;
    float s = 0.f;
    for (int k = 0; k < CIN; k++) s += W[c * CIN + k] * g_sx[b * CIN + k];
    (which ? g_bph : g_bth)[b * C1 + c] = s;
}

// ------------- b2e = b2 + Wf·bg  (per batch) -------------
__global__ void b2e_kernel(const float* __restrict__ b2, const float* __restrict__ bg)
{
    int idx = blockIdx.x * 256 + threadIdx.x;   // 8*512
    int b = idx >> 9, c = idx & 511;
    float s = b2[c];
    long base = ((long)b << 17) + (long)c * C1;
    for (int d = 0; d < C1; d++)
        s += bg[d] * (__bfloat162float(g_Wfh[base + d]) + __bfloat162float(g_Wfm[base + d]));
    g_b2e[idx] = s;
}

// ------------- b3e = W3·b2e + b3  (per batch) -------------
__global__ void b3e_kernel(const float* __restrict__ W3, const float* __restrict__ b3)
{
    int idx = blockIdx.x * 256 + threadIdx.x;   // 8*128
    int b = idx >> 7, d = idx & 127;
    float s = b3[d];
    for (int c = 0; c < CIN; c++) s += g_b2e[b * CIN + c] * W3[d * CIN + c];
    g_b3e[idx] = s;
}

// ------------- softmax over f rows (sum split-K partials + bias corr), f^T bf16 out -------------
__global__ void softmaxT(const float* __restrict__ bth_bias, const float* __restrict__ bph_bias)
{
    int row = blockIdx.x, t = threadIdx.x;
    int b = row >> 8, c = row & 255;
    long il = (long)c * 256 + t;
    float v = 0.f;
#pragma unroll
    for (int s = 0; s < 4; s++) v += g_Fp4[(((long)(b * 4 + s)) << 16) + il];
    v += bth_bias[c] * g_bph[b * C1 + t]
       + bph_bias[t] * g_bth[b * C1 + c]
       + (float)NN * bth_bias[c] * bph_bias[t];
    __shared__ float sh[256];
    sh[t] = v; __syncthreads();
    for (int o = 128; o; o >>= 1) { if (t < o) sh[t] = fmaxf(sh[t], sh[t + o]); __syncthreads(); }
    float mx = sh[0]; __syncthreads();
    float e = expf(v - mx);
    sh[t] = e; __syncthreads();
    for (int o = 128; o; o >>= 1) { if (t < o) sh[t] += sh[t + o]; __syncthreads(); }
    float r = e / sh[0];
    long o2 = ((long)b << 16) + (long)t * 256 + c;   // f^T[d=t, c]
    bf16 h = __float2bfloat16(r);
    g_Fh[o2] = h;
    g_Fm[o2] = __float2bfloat16(r - __bfloat162float(h));
}

// ------------- fused dist -> softmax(A) -> E accumulation -------------
__global__ __launch_bounds__(256) void encode_kernel(
    const float* __restrict__ ZDt,
    const float* __restrict__ codewords, const float* __restrict__ scale,
    float* __restrict__ Eacc, float* __restrict__ Asum)
{
    int b = blockIdx.y;
    __shared__ float cs[KK][DD + 1];
    __shared__ float cn[KK], sc[KK];
    __shared__ float xs[DD][33];
    __shared__ float Ash[8][KK];
    int tid = threadIdx.x, lane = tid & 31, wid = tid >> 5;

    for (int i = tid; i < KK * DD; i += 256) cs[i >> 7][i & 127] = codewords[i];
    if (tid < KK) sc[tid] = scale[tid];
    __syncthreads();
    if (tid < KK) {
        float s = 0.f;
        for (int d = 0; d < DD; d++) { float c = cs[tid][d]; s += c * c; }
        cn[tid] = s;
    }
    __syncthreads();

    float ereg[16];
#pragma unroll
    for (int i = 0; i < 16; i++) ereg[i] = 0.f;
    float asum_local = 0.f;
    int myk = tid >> 3, myd0 = tid & 7;

    for (int t = blockIdx.x; t < NN / 32; t += gridDim.x) {
        int n0 = t * 32;
#pragma unroll
        for (int r = 0; r < 4; r++) {
            int idx = r * 256 + tid;
            int n = idx >> 5, d4 = (idx & 31) * 4;
            float4 v = *(const float4*)(ZDt + ((long)b * NN + n0 + n) * DD + d4);
            xs[d4][n] = v.x; xs[d4 + 1][n] = v.y; xs[d4 + 2][n] = v.z; xs[d4 + 3][n] = v.w;
        }
        __syncthreads();
        for (int round = 0; round < 4; round++) {
            int n = round * 8 + wid;
            float xx = 0.f;
            for (int d = lane; d < DD; d += 32) { float x = xs[d][n]; xx += x * x; }
            for (int o = 16; o; o >>= 1) xx += __shfl_xor_sync(0xffffffffu, xx, o);
            float dot = 0.f;
#pragma unroll 8
            for (int d = 0; d < DD; d++) dot += xs[d][n] * cs[lane][d];
            float s = sc[lane] * (xx - 2.f * dot + cn[lane]);
            float mx = s;
            for (int o = 16; o; o >>= 1) mx = fmaxf(mx, __shfl_xor_sync(0xffffffffu, mx, o));
            float e = __expf(s - mx);
            float ssum = e;
            for (int o = 16; o; o >>= 1) ssum += __shfl_xor_sync(0xffffffffu, ssum, o);
            float a = e / ssum;
            Ash[wid][lane] = a;
            asum_local += a;
            __syncthreads();
#pragma unroll
            for (int nn2 = 0; nn2 < 8; nn2++) {
                float av = Ash[nn2][myk];
                int ncol = round * 8 + nn2;
#pragma unroll
                for (int i = 0; i < 16; i++)
                    ereg[i] += av * xs[myd0 + 8 * i][ncol];
            }
            __syncthreads();
        }
    }
#pragma unroll
    for (int i = 0; i < 16; i++)
        atomicAdd(&Eacc[((long)b * KK + myk) * DD + myd0 + 8 * i], ereg[i]);
    atomicAdd(&Asum[b * KK + lane], asum_local);
}

// ------------- BN over K + Es -------------
__global__ void bn_es_kernel(const float* __restrict__ Eacc, const float* __restrict__ Asum,
                             const float* __restrict__ codewords, float* __restrict__ Es)
{
    int k = blockIdx.x, tid = threadIdx.x;
    __shared__ double shs[256], shs2[256];
    float vals[4];
    double s = 0.0, s2 = 0.0;
#pragma unroll
    for (int i = 0; i < 4; i++) {
        int idx = tid + i * 256;
        int b = idx >> 7, d = idx & 127;
        float v = Eacc[((long)b * KK + k) * DD + d] - Asum[b * KK + k] * codewords[k * DD + d];
        vals[i] = v; s += v; s2 += (double)v * v;
    }
    shs[tid] = s; shs2[tid] = s2; __syncthreads();
    for (int o = 128; o; o >>= 1) {
        if (tid < o) { shs[tid] += shs[tid + o]; shs2[tid] += shs2[tid + o]; }
        __syncthreads();
    }
    double mean = shs[0] / 1024.0;
    double var = shs2[0] / 1024.0 - mean * mean;
    float inv = rsqrtf((float)var + 1e-5f);
    float mf = (float)mean;
#pragma unroll
    for (int i = 0; i < 4; i++) {
        int idx = tid + i * 256;
        int b = idx >> 7, d = idx & 127;
        float e = (vals[i] - mf) * inv;
        if (e > 0.f) atomicAdd(&Es[b * DD + d], e);
    }
}

// ------------- gamma = sigmoid(Es @ W_fc^T + b_fc) -------------
__global__ void gamma_kernel(const float* __restrict__ Es, const float* __restrict__ W_fc,
                             const float* __restrict__ b_fc, float* __restrict__ gam)
{
    int idx = blockIdx.x * blockDim.x + threadIdx.x;
    int b = idx / CIN, c = idx % CIN;
    float s = b_fc[c];
    for (int d = 0; d < DD; d++) s += Es[b * DD + d] * W_fc[c * DD + d];
    gam[idx] = 1.f / (1.f + expf(-s));
}

// ------------- launch -------------
#define GA(T, p, s) T* p; cudaGetSymbolAddress((void**)&p, s)

extern "C" void kernel_launch(void* const* d_in, const int* in_sizes, int n_in,
                              void* d_out, int out_size)
{
    const float* X        = (const float*)d_in[0];
    const float* W_theta  = (const float*)d_in[1];
    const float* b_theta  = (const float*)d_in[2];
    const float* W_phi    = (const float*)d_in[3];
    const float* b_phi    = (const float*)d_in[4];
    const float* W_g      = (const float*)d_in[5];
    const float* b_g      = (const float*)d_in[6];
    const float* W2       = (const float*)d_in[7];
    const float* b2       = (const float*)d_in[8];
    const float* W3       = (const float*)d_in[9];
    const float* b3       = (const float*)d_in[10];
    const float* codewords= (const float*)d_in[11];
    const float* scale    = (const float*)d_in[12];
    const float* W_fc     = (const float*)d_in[13];
    const float* b_fc     = (const float*)d_in[14];

    GA(bf16, Xh, g_Xh); GA(bf16, Xm, g_Xm);
    GA(bf16, Xch, g_Xch); GA(bf16, Xcm, g_Xcm); GA(bf16, Xcl, g_Xcl);
    GA(bf16, Wth, g_Wth); GA(bf16, Wtm, g_Wtm); GA(bf16, Wtl, g_Wtl);
    GA(bf16, Wph, g_Wph); GA(bf16, Wpm, g_Wpm); GA(bf16, Wpl, g_Wpl);
    GA(bf16, WgTh, g_WgTh); GA(bf16, WgTm, g_WgTm);
    GA(bf16, W2h, g_W2h); GA(bf16, W2m, g_W2m);
    GA(bf16, W3h, g_W3h); GA(bf16, W3m, g_W3m);
    GA(float, Gp, g_Gp);
    GA(bf16, GRh, g_GRh); GA(bf16, GRm, g_GRm); GA(bf16, GRl, g_GRl);
    GA(float, T1p, g_T1p);
    GA(bf16, T1h, g_T1h); GA(bf16, T1m, g_T1m); GA(bf16, T1l, g_T1l);
    GA(float, Fp4, g_Fp4);
    GA(bf16, Fh, g_Fh); GA(bf16, Fm, g_Fm);
    GA(bf16, Wfh, g_Wfh); GA(bf16, Wfm, g_Wfm);
    GA(float, Mf, g_Mf);
    GA(bf16, Mkh, g_Mkh); GA(bf16, Mkm, g_Mkm);
    GA(bf16, Mch, g_Mch); GA(bf16, Mcm, g_Mcm);
    GA(bf16, M2h, g_M2h); GA(bf16, M2m, g_M2m);
    GA(float, b2e, g_b2e); GA(float, b3e, g_b3e);
    GA(float, ZDt, g_ZDt);
    GA(float, Eacc, g_Eacc); GA(float, Asum, g_Asum);
    GA(float, Es, g_Es); GA(float, gamB, g_gam);

    const int SM6 = 2 * 6 * 8192;   // 98304
    const int SM3 = 2 * 4 * 8192;   // 65536
    cudaFuncSetAttribute((const void*)mma_gemm<6, false>, cudaFuncAttributeMaxDynamicSharedMemorySize, SM6);
    cudaFuncSetAttribute((const void*)mma_gemm<6, true>,  cudaFuncAttributeMaxDynamicSharedMemorySize, SM6);
    cudaFuncSetAttribute((const void*)mma_gemm<3, false>, cudaFuncAttributeMaxDynamicSharedMemorySize, SM3);

    split_all<<<512, 256>>>(W_theta, W_phi, W_g, W2, W3);   // also zeroes accumulators
    tsplit2<<<dim3(288, 16, BB), dim3(32, 8)>>>(X);

    // Gram: G = X·X^T per batch, lower-triangle tiles, split-K=18 (KS=512)
    mma_gemm<6, true><<<dim3(10, 1, BB * GS), 256, SM6>>>(
        Xch, Xcm, Xcl, NN, (long)CIN * NN, Xch, Xcm, Xcl, NN, (long)CIN * NN,
        Gp, nullptr, nullptr, CIN, (long)CIN * CIN,
        nullptr, 0, nullptr, 0, nullptr, 0, nullptr, 0, 16, GS);
    gram_reduce<<<8192, 256>>>();

    // T1 = Wphi @ G (256x512/batch), x6, split-K=4 -> fp32 partials
    mma_gemm<6, false><<<dim3(4, 2, BB * 4), 256, SM6>>>(
        Wph, Wpm, Wpl, CIN, 0, GRh, GRm, GRl, CIN, (long)CIN * CIN,
        T1p, nullptr, nullptr, CIN, 131072L,
        nullptr, 0, nullptr, 0, nullptr, 0, nullptr, 0, 4, 4);
    t1_reduce<<<4096, 256>>>();

    // f = Wtheta @ T1^T (256x256/batch), x6, split-K=4 -> fp32 partials
    mma_gemm<6, false><<<dim3(2, 2, BB * 4), 256, SM6>>>(
        Wth, Wtm, Wtl, CIN, 0, T1h, T1m, T1l, CIN, 131072L,
        Fp4, nullptr, nullptr, C1, 65536L,
        nullptr, 0, nullptr, 0, nullptr, 0, nullptr, 0, 4, 4);

    bcorr<<<16, 256>>>(W_theta, W_phi);
    softmaxT<<<BB * C1, 256>>>(b_theta, b_phi);

    // Wf = W2 @ f^T: (512 x 256)/batch, x3 -> h/m parts
    mma_gemm<3, false><<<dim3(2, 4, BB), 256, SM3>>>(
        W2h, W2m, nullptr, C1, 0, Fh, Fm, nullptr, C1, 65536L,
        nullptr, Wfh, Wfm, C1, 131072L,
        nullptr, 0, nullptr, 0, nullptr, 0, nullptr, 0, 8, 1);

    b2e_kernel<<<16, 256>>>(b2, b_g);
    b3e_kernel<<<4, 256>>>(W3, b3);

    // M[k,cc] = Wg^T · Wf^T : A=WgT (k,d), B=Wf (cc,d), K=256, fp32 out
    mma_gemm<3, false><<<dim3(4, 4, BB), 256, SM3>>>(
        WgTh, WgTm, nullptr, C1, 0, Wfh, Wfm, nullptr, C1, 131072L,
        Mf, nullptr, nullptr, CIN, 262144L,
        nullptr, 0, nullptr, 0, nullptr, 0, nullptr, 0, 8, 1);
    msplit<<<8192, 256>>>();

    // M2^T[d,k] = W3 · (M+I): A=W3 (d,c), B=Mk (k,c), K=512, +W3 residual -> h/m parts
    mma_gemm<3, false><<<dim3(4, 1, BB), 256, SM3>>>(
        W3h, W3m, nullptr, CIN, 0, Mkh, Mkm, nullptr, CIN, 262144L,
        nullptr, M2h, M2m, CIN, 65536L,
        nullptr, 0, nullptr, 0, W3, 0, nullptr, 0, 16, 1);

    // z_ (n rows, d contig): C[n,d] = X_t·M2 + b3e[d] : A=X_t (n,k), B=M2^T (d,k), K=512
    mma_gemm<3, false><<<dim3(1, 72, BB), 256, SM3>>>(
        Xh, Xm, nullptr, CIN, (long)NN * CIN, M2h, M2m, nullptr, CIN, 65536L,
        ZDt, nullptr, nullptr, DD, (long)NN * DD,
        b3e, DD, nullptr, 0, nullptr, 0, nullptr, 0, 16, 1);

    encode_kernel<<<dim3(96, BB), 256>>>(ZDt, codewords, scale, Eacc, Asum);
    bn_es_kernel<<<KK, 256>>>(Eacc, Asum, codewords, Es);
    gamma_kernel<<<(BB * CIN) / 256, 256>>>(Es, W_fc, b_fc, gamB);

    // out (B,C,N): C[cc,n] = ((M+I)^T·X_t^T + b2e[cc]) * gamma[cc]  -> d_out directly
    mma_gemm<3, false><<<dim3(72, 4, BB), 256, SM3>>>(
        Mch, Mcm, nullptr, CIN, 262144L, Xh, Xm, nullptr, CIN, (long)NN * CIN,
        (float*)d_out, nullptr, nullptr, NN, (long)CIN * NN,
        nullptr, 0, b2e, CIN, nullptr, 0, gamB, CIN, 16, 1);
}

// round 13
// speedup vs baseline: 1.0528x; 1.0147x over previous
#include <cuda_runtime.h>
#include <cuda_bf16.h>
#include <math.h>
#include <stdint.h>

#define BB 8
#define CIN 512
#define C1 256
#define DD 128
#define KK 32
#define NN 9216
#define ROWS (BB*NN)
#define GS 18            // Gram split-K slices
typedef __nv_bfloat16 bf16;
typedef unsigned int u32;

// ------------- scratch (device globals) -------------
__device__ bf16 g_Xh[ROWS*CIN], g_Xm[ROWS*CIN];                      // X (N-major rows n, k contig)
__device__ bf16 g_Xch[ROWS*CIN], g_Xcm[ROWS*CIN], g_Xcl[ROWS*CIN];   // X (C-major rows ch, n contig)
__device__ bf16 g_Wth[C1*CIN], g_Wtm[C1*CIN], g_Wtl[C1*CIN];
__device__ bf16 g_Wph[C1*CIN], g_Wpm[C1*CIN], g_Wpl[C1*CIN];
__device__ bf16 g_WgTh[CIN*C1], g_WgTm[CIN*C1];                      // Wg^T (k rows, d contig)
__device__ bf16 g_W2h[CIN*C1], g_W2m[CIN*C1];
__device__ bf16 g_W3h[DD*CIN], g_W3m[DD*CIN];
__device__ float g_Gp[(BB*GS)*CIN*CIN];                              // Gram split-K partials
__device__ bf16 g_GRh[BB*CIN*CIN], g_GRm[BB*CIN*CIN], g_GRl[BB*CIN*CIN];
__device__ float g_T1p[BB*4*C1*CIN];                                 // T1 split-K partials
__device__ bf16 g_T1h[BB*C1*CIN], g_T1m[BB*C1*CIN], g_T1l[BB*C1*CIN];
__device__ float g_Fp4[BB*4*C1*C1];                                  // f split-K partials
__device__ bf16 g_Fh[BB*C1*C1], g_Fm[BB*C1*C1];                      // f^T parts (d rows, c contig)
__device__ bf16 g_Wfh[BB*CIN*C1], g_Wfm[BB*CIN*C1];                  // Wf = W2·f (cc rows, d contig)
__device__ float g_Mf[BB*CIN*CIN];                                   // M fp32 (k rows, cc contig)
__device__ bf16 g_Mkh[BB*CIN*CIN], g_Mkm[BB*CIN*CIN];                // M (k rows, cc contig)
__device__ bf16 g_Mch[BB*CIN*CIN], g_Mcm[BB*CIN*CIN];                // (M+I)^T (cc rows, k contig)
__device__ bf16 g_M2h[BB*DD*CIN], g_M2m[BB*DD*CIN];                  // M2^T (d rows, k contig)
__device__ float g_b2e[BB*CIN];                                      // b2 + Wf·bg
__device__ float g_b3e[BB*DD];                                       // W3·b2e + b3
__device__ float g_ZDt[ROWS*DD];                                     // z_ rows n, d contig
__device__ float g_sx[BB*CIN];
__device__ float g_bth[BB*C1], g_bph[BB*C1];
__device__ float g_Eacc[BB*KK*DD], g_Asum[BB*KK], g_Es[BB*DD], g_gam[BB*CIN];

// ------------- helpers -------------
__device__ __forceinline__ u32 smem_u32(const void* p) {
    u32 a;
    asm("{ .reg .u64 t; cvta.to.shared.u64 t, %1; cvt.u32.u64 %0, t; }" : "=r"(a) : "l"(p));
    return a;
}
__device__ __forceinline__ void cp16(u32 d, const void* s) {
    asm volatile("cp.async.cg.shared.global [%0], [%1], 16;" :: "r"(d), "l"(s));
}
__device__ __forceinline__ void cp_commit() { asm volatile("cp.async.commit_group;" ::: "memory"); }
template<int N> __device__ __forceinline__ void cp_waitg() {
    asm volatile("cp.async.wait_group %0;" :: "n"(N) : "memory");
}
__device__ __forceinline__ void ldm_x4(u32* r, u32 addr) {
    asm volatile("ldmatrix.sync.aligned.m8n8.x4.shared.b16 {%0,%1,%2,%3}, [%4];"
        : "=r"(r[0]), "=r"(r[1]), "=r"(r[2]), "=r"(r[3]) : "r"(addr));
}
__device__ __forceinline__ void mma16816(float* d, const u32* a, const u32* b) {
    asm volatile(
        "mma.sync.aligned.m16n8k16.row.col.f32.bf16.bf16.f32 "
        "{%0,%1,%2,%3}, {%4,%5,%6,%7}, {%8,%9}, {%0,%1,%2,%3};"
        : "+f"(d[0]), "+f"(d[1]), "+f"(d[2]), "+f"(d[3])
        : "r"(a[0]), "r"(a[1]), "r"(a[2]), "r"(a[3]), "r"(b[0]), "r"(b[1]));
}
__device__ __forceinline__ void st2bf(bf16* p, long i, float a, float b_) {
    __nv_bfloat162 v(__float2bfloat16(a), __float2bfloat16(b_));
    *(u32*)(p + i) = *(u32*)&v;
}

// ============ mma.sync bf16-split GEMM, product-shared tiles, BK=32 ============
// C[z; m, n] = sum over triangular products A_pa * B_pb (pa+pb<NB), K-major.
// SYM: blockIdx.x indexes lower-triangle 128x128 tile pairs of a 512x512 output.
// NSTG: cp.async ring depth (2 for x6, 3 for x3).
// out = ((acc + biasR[row] + biasC[col] + Rf[row,col]) * scaleR[row])
template<int NPROD, bool SYM, int NSTG>
__global__ __launch_bounds__(256, 2) void mma_gemm(
    const bf16* __restrict__ Ah, const bf16* __restrict__ Am, const bf16* __restrict__ Al,
    int lda, long sAb,
    const bf16* __restrict__ Bh, const bf16* __restrict__ Bm, const bf16* __restrict__ Bl,
    int ldb, long sBb,
    float* __restrict__ C, bf16* __restrict__ Ch, bf16* __restrict__ Cm,
    int ldc, long sCz,
    const float* __restrict__ biasC, long sBC,
    const float* __restrict__ biasR, long sBR,
    const float* __restrict__ Rf, long sRz,
    const float* __restrict__ scaleR, long sSR,
    int NCH, int S)
{
    constexpr int NA = (NPROD == 6) ? 3 : 2;
    constexpr int NB = NA;
    constexpr int STAGE = (NA + NB) * 8192;

    extern __shared__ __align__(16) char smem[];
    const u32 sbase = smem_u32(smem);

    const int tid = threadIdx.x, lane = tid & 31, wid = tid >> 5;
    const int wm = wid & 1, wn = wid >> 1;
    const int z = blockIdx.z, b = z / S, s = z % S;
    int bx, by;
    if (SYM) {
        int p = blockIdx.x;
        by = (p < 1) ? 0 : (p < 3) ? 1 : (p < 6) ? 2 : 3;
        bx = p - (by * (by + 1)) / 2;
    } else { bx = blockIdx.x; by = blockIdx.y; }
    const long m0 = (long)by * 128;
    const int n0 = bx * 128;
    const int KS = NCH * 32;

    const long abase = (long)b * sAb + m0 * lda + (long)s * KS;
    const long bbase = (long)b * sBb + (long)n0 * ldb + (long)s * KS;

    const bf16* APT[3] = {Ah, Am, Al};
    const bf16* BPT[3] = {Bh, Bm, Bl};

    float acc[4][4][4];
#pragma unroll
    for (int i = 0; i < 4; i++)
#pragma unroll
        for (int j = 0; j < 4; j++)
#pragma unroll
            for (int r = 0; r < 4; r++) acc[i][j][r] = 0.f;

    const int row2 = tid >> 1, lq = tid & 1;
    const int sw = (row2 >> 1) & 3;
    const u32 c0off = (u32)(row2 * 64 + (((lq * 2 + 0) ^ sw) << 4));
    const u32 c1off = (u32)(row2 * 64 + (((lq * 2 + 1) ^ sw) << 4));

    auto issue = [&](int c) {
        int k0 = c * 32;
        u32 sd = sbase + (c % NSTG) * STAGE;
#pragma unroll
        for (int p = 0; p < NA; p++) {
            const bf16* ap = APT[p] + abase + k0 + (long)row2 * lda + lq * 16;
            cp16(sd + p * 8192 + c0off, ap);
            cp16(sd + p * 8192 + c1off, ap + 8);
        }
#pragma unroll
        for (int p = 0; p < NB; p++) {
            const bf16* bp = BPT[p] + bbase + k0 + (long)row2 * ldb + lq * 16;
            cp16(sd + (NA + p) * 8192 + c0off, bp);
            cp16(sd + (NA + p) * 8192 + c1off, bp + 8);
        }
        cp_commit();
    };

    u32 aoff[4], boff[2];
#pragma unroll
    for (int t = 0; t < 4; t++) {
        int ra = wm * 64 + t * 16 + (lane & 15);
        int j = lane >> 4;
        aoff[t] = (u32)(ra * 64 + ((j ^ ((ra >> 1) & 3)) << 4));
    }
#pragma unroll
    for (int u = 0; u < 2; u++) {
        int rb = wn * 32 + u * 16 + (lane & 7) + ((lane >> 4) & 1) * 8;
        int j = (lane >> 3) & 1;
        boff[u] = (u32)(rb * 64 + ((j ^ ((rb >> 1) & 3)) << 4));
    }

#pragma unroll
    for (int p = 0; p < NSTG - 1; p++) if (p < NCH) issue(p);

    for (int c = 0; c < NCH; c++) {
        if (c + NSTG - 1 < NCH) { issue(c + NSTG - 1); cp_waitg<NSTG - 1>(); }
        else if (NSTG == 3 && c + 1 < NCH) cp_waitg<1>();
        else cp_waitg<0>();
        __syncthreads();
        u32 sA = sbase + (c % NSTG) * STAGE;
        u32 sB = sA + NA * 8192;
#pragma unroll
        for (int kk = 0; kk < 2; kk++) {
            u32 kx = kk << 5;
            u32 bfr[NB][2][4];
#pragma unroll
            for (int pb = 0; pb < NB; pb++)
#pragma unroll
                for (int u = 0; u < 2; u++)
                    ldm_x4(bfr[pb][u], sB + pb * 8192 + (boff[u] ^ kx));
#pragma unroll
            for (int pa = 0; pa < NA; pa++) {
                u32 af[4][4];
#pragma unroll
                for (int t = 0; t < 4; t++)
                    ldm_x4(af[t], sA + pa * 8192 + (aoff[t] ^ kx));
#pragma unroll
                for (int pb = 0; pb < NB; pb++) {
                    if (pa + pb < NB) {
#pragma unroll
                        for (int mi = 0; mi < 4; mi++)
#pragma unroll
                            for (int ni = 0; ni < 4; ni++)
                                mma16816(acc[mi][ni], af[mi], &bfr[pb][ni >> 1][(ni & 1) * 2]);
                    }
                }
            }
        }
        __syncthreads();
    }

    // ---- epilogue ----
    const int mrow = lane >> 2, nc2 = (lane & 3) * 2;
#pragma unroll
    for (int mi = 0; mi < 4; mi++) {
#pragma unroll
        for (int rp = 0; rp < 2; rp++) {
            long row = m0 + wm * 64 + mi * 16 + mrow + rp * 8;
            long coff = (long)z * sCz + row * ldc;
            long roff = (long)b * sRz + row * ldc;
            float br = biasR ? biasR[b * sBR + row] : 0.f;
            float sr = scaleR ? scaleR[b * sSR + row] : 1.f;
#pragma unroll
            for (int ni = 0; ni < 4; ni++) {
                int col = n0 + wn * 32 + ni * 8 + nc2;
                float v0 = acc[mi][ni][rp * 2 + 0] + br;
                float v1 = acc[mi][ni][rp * 2 + 1] + br;
                if (biasC) { v0 += biasC[b * sBC + col]; v1 += biasC[b * sBC + col + 1]; }
                if (Rf) {
                    float2 r = *(const float2*)&Rf[roff + col];
                    v0 += r.x; v1 += r.y;
                }
                v0 *= sr; v1 *= sr;
                if (C) *(float2*)&C[coff + col] = make_float2(v0, v1);
                if (Ch) {
                    float h0 = __bfloat162float(__float2bfloat16(v0));
                    float h1 = __bfloat162float(__float2bfloat16(v1));
                    st2bf(Ch, coff + col, v0, v1);
                    st2bf(Cm, coff + col, v0 - h0, v1 - h1);
                }
            }
        }
    }
}

// ------------- X: transpose+split (N-major h/m) AND straight split (C-major h/m/l) + row sums -------------
__global__ void tsplit2(const float* __restrict__ src)
{
    __shared__ float ts[32][33];
    int b = blockIdx.z;
    long o = (long)b * CIN * NN;
    int c0 = blockIdx.x * 32, r0 = blockIdx.y * 32;   // c0: n-dim, r0: channel
    int tx = threadIdx.x, ty = threadIdx.y;
#pragma unroll
    for (int i = 0; i < 4; i++) {
        int ch = r0 + ty + i * 8;
        long sidx = o + (long)ch * NN + c0 + tx;
        float v = src[sidx];
        ts[ty + i * 8][tx] = v;
        bf16 hh = __float2bfloat16(v);
        float r1 = v - __bfloat162float(hh);
        bf16 mm = __float2bfloat16(r1);
        g_Xch[sidx] = hh; g_Xcm[sidx] = mm;
        g_Xcl[sidx] = __float2bfloat16(r1 - __bfloat162float(mm));
        float sum = v;
#pragma unroll
        for (int off = 16; off; off >>= 1) sum += __shfl_xor_sync(0xffffffffu, sum, off);
        if (tx == 0) atomicAdd(&g_sx[b * CIN + ch], sum);
    }
    __syncthreads();
    // v = ts[tx][ty+i*8] = X[ch=r0+tx][n=c0+ty+i*8]; store at X_t[n][ch]
#pragma unroll
    for (int i = 0; i < 4; i++) {
        int n = c0 + ty + i * 8;
        float v = ts[tx][ty + i * 8];
        long tdx = (long)b * NN * CIN + (long)n * CIN + (r0 + tx);
        bf16 hh = __float2bfloat16(v);
        g_Xh[tdx] = hh;
        g_Xm[tdx] = __float2bfloat16(v - __bfloat162float(hh));
    }
}

// ------------- weight splits + accumulator zeroing (one launch; runs FIRST) -------------
__global__ void split_all(const float* __restrict__ Wt, const float* __restrict__ Wp,
                          const float* __restrict__ Wg, const float* __restrict__ W2,
                          const float* __restrict__ W3)
{
    int i = blockIdx.x * 256 + threadIdx.x;
    if (i < BB * KK * DD) g_Eacc[i] = 0.f;
    if (i < BB * KK)      g_Asum[i] = 0.f;
    if (i < BB * DD)      g_Es[i]   = 0.f;
    if (i < BB * CIN)     g_sx[i]   = 0.f;
    if (i < C1 * CIN) {
        float v = Wt[i];
        bf16 h = __float2bfloat16(v); float r1 = v - __bfloat162float(h);
        bf16 m = __float2bfloat16(r1);
        g_Wth[i] = h; g_Wtm[i] = m; g_Wtl[i] = __float2bfloat16(r1 - __bfloat162float(m));
        v = Wp[i];
        h = __float2bfloat16(v); r1 = v - __bfloat162float(h);
        m = __float2bfloat16(r1);
        g_Wph[i] = h; g_Wpm[i] = m; g_Wpl[i] = __float2bfloat16(r1 - __bfloat162float(m));
        // Wg: transpose into (k rows, d contig)
        v = Wg[i];
        int d = i >> 9, k = i & 511;      // Wg[d][k], row-major 256x512
        h = __float2bfloat16(v);
        g_WgTh[k * C1 + d] = h;
        g_WgTm[k * C1 + d] = __float2bfloat16(v - __bfloat162float(h));
        v = W2[i];
        h = __float2bfloat16(v);
        g_W2h[i] = h; g_W2m[i] = __float2bfloat16(v - __bfloat162float(h));
    }
    if (i < DD * CIN) {
        float v = W3[i];
        bf16 h = __float2bfloat16(v);
        g_W3h[i] = h; g_W3m[i] = __float2bfloat16(v - __bfloat162float(h));
    }
}

// ------------- reduce Gram split-K partials (triangle-only reads, mirror writes) -------------
__global__ void gram_reduce()
{
    long idx = (long)blockIdx.x * 256 + threadIdx.x;   // 8*512*512
    int b = (int)(idx >> 18);
    int rem = (int)(idx & 262143);
    int c1 = rem >> 9, c2 = rem & 511;
    int t1 = c1 >> 7, t2 = c2 >> 7;
    if (t1 < t2) return;                                // upper-tri tiles handled by mirror
    float v = 0.f;
#pragma unroll
    for (int s = 0; s < GS; s++) v += g_Gp[(((long)(b * GS + s)) << 18) + (long)rem];
    bf16 h = __float2bfloat16(v);
    float r1 = v - __bfloat162float(h);
    bf16 m = __float2bfloat16(r1);
    bf16 l = __float2bfloat16(r1 - __bfloat162float(m));
    g_GRh[idx] = h; g_GRm[idx] = m; g_GRl[idx] = l;
    if (t1 > t2) {                                      // mirror into the upper-tri tile
        long mdx = (((long)b) << 18) + ((long)c2 << 9) + c1;
        g_GRh[mdx] = h; g_GRm[mdx] = m; g_GRl[mdx] = l;
    }
}

// ------------- reduce T1 split-K partials + 3-way split -------------
__global__ void t1_reduce()
{
    long idx = (long)blockIdx.x * 256 + threadIdx.x;   // 8*131072
    int b = (int)(idx >> 17);
    long il = idx & 131071;
    float v = 0.f;
#pragma unroll
    for (int s = 0; s < 4; s++) v += g_T1p[(((long)(b * 4 + s)) << 17) + il];
    bf16 h = __float2bfloat16(v);
    float r1 = v - __bfloat162float(h);
    bf16 m = __float2bfloat16(r1);
    g_T1h[idx] = h; g_T1m[idx] = m;
    g_T1l[idx] = __float2bfloat16(r1 - __bfloat162float(m));
}

// ------------- M split: Mk = M (k rows), Mc = (M+I)^T (cc rows) -------------
__global__ void msplit()
{
    long idx = (long)blockIdx.x * 256 + threadIdx.x;   // 8*512*512
    int b = (int)(idx >> 18);
    int rem = (int)(idx & 262143);
    int k = rem >> 9, cc = rem & 511;
    float v = g_Mf[idx];
    bf16 h = __float2bfloat16(v);
    bf16 m = __float2bfloat16(v - __bfloat162float(h));
    g_Mkh[idx] = h; g_Mkm[idx] = m;                     // M (k rows, cc contig), no I
    float v2 = v + (k == cc ? 1.f : 0.f);               // fold +X residual into M
    bf16 h2 = __float2bfloat16(v2);
    bf16 m2 = __float2bfloat16(v2 - __bfloat162float(h2));
    long tdx = (((long)b) << 18) + ((long)cc << 9) + k; // (cc rows, k contig)
    g_Mch[tdx] = h2; g_Mcm[tdx] = m2;
}

// ------------- bias rank-1 corrections: bth = Wtheta*sx, bph = Wphi*sx -------------
__global__ void bcorr(const float* __restrict__ Wt, const float* __restrict__ Wp)
{
    int idx = blockIdx.x * 256 + threadIdx.x;   // 2*8*256
    int which = idx >> 11;
    int r = idx & 2047;
    int b = r >> 8, c = r & 255;
    const float* W = which ? Wp : Wt;
    float s = 0.f;
    for (int k = 0; k < CIN; k++) s += W[c * CIN + k] * g_sx[b * CIN + k];
    (which ? g_bph : g_bth)[b * C1 + c] = s;
}

// ------------- b2e = b2 + Wf·bg  (per batch) -------------
__global__ void b2e_kernel(const float* __restrict__ b2, const float* __restrict__ bg)
{
    int idx = blockIdx.x * 256 + threadIdx.x;   // 8*512
    int b = idx >> 9, c = idx & 511;
    float s = b2[c];
    long base = ((long)b << 17) + (long)c * C1;
    for (int d = 0; d < C1; d++)
        s += bg[d] * (__bfloat162float(g_Wfh[base + d]) + __bfloat162float(g_Wfm[base + d]));
    g_b2e[idx] = s;
}

// ------------- b3e = W3·b2e + b3  (per batch) -------------
__global__ void b3e_kernel(const float* __restrict__ W3, const float* __restrict__ b3)
{
    int idx = blockIdx.x * 256 + threadIdx.x;   // 8*128
    int b = idx >> 7, d = idx & 127;
    float s = b3[d];
    for (int c = 0; c < CIN; c++) s += g_b2e[b * CIN + c] * W3[d * CIN + c];
    g_b3e[idx] = s;
}

// ------------- softmax over f rows (sum split-K partials + bias corr), f^T bf16 out -------------
__global__ void softmaxT(const float* __restrict__ bth_bias, const float* __restrict__ bph_bias)
{
    int row = blockIdx.x, t = threadIdx.x;
    int b = row >> 8, c = row & 255;
    long il = (long)c * 256 + t;
    float v = 0.f;
#pragma unroll
    for (int s = 0; s < 4; s++) v += g_Fp4[(((long)(b * 4 + s)) << 16) + il];
    v += bth_bias[c] * g_bph[b * C1 + t]
       + bph_bias[t] * g_bth[b * C1 + c]
       + (float)NN * bth_bias[c] * bph_bias[t];
    __shared__ float sh[256];
    sh[t] = v; __syncthreads();
    for (int o = 128; o; o >>= 1) { if (t < o) sh[t] = fmaxf(sh[t], sh[t + o]); __syncthreads(); }
    float mx = sh[0]; __syncthreads();
    float e = expf(v - mx);
    sh[t] = e; __syncthreads();
    for (int o = 128; o; o >>= 1) { if (t < o) sh[t] += sh[t + o]; __syncthreads(); }
    float r = e / sh[0];
    long o2 = ((long)b << 16) + (long)t * 256 + c;   // f^T[d=t, c]
    bf16 h = __float2bfloat16(r);
    g_Fh[o2] = h;
    g_Fm[o2] = __float2bfloat16(r - __bfloat162float(h));
}

// ------------- fused dist -> softmax(A) -> E accumulation -------------
__global__ __launch_bounds__(256) void encode_kernel(
    const float* __restrict__ ZDt,
    const float* __restrict__ codewords, const float* __restrict__ scale,
    float* __restrict__ Eacc, float* __restrict__ Asum)
{
    int b = blockIdx.y;
    __shared__ float cs[KK][DD + 1];
    __shared__ float cn[KK], sc[KK];
    __shared__ float xs[DD][33];
    __shared__ float Ash[8][KK];
    int tid = threadIdx.x, lane = tid & 31, wid = tid >> 5;

    for (int i = tid; i < KK * DD; i += 256) cs[i >> 7][i & 127] = codewords[i];
    if (tid < KK) sc[tid] = scale[tid];
    __syncthreads();
    if (tid < KK) {
        float s = 0.f;
        for (int d = 0; d < DD; d++) { float c = cs[tid][d]; s += c * c; }
        cn[tid] = s;
    }
    __syncthreads();

    float ereg[16];
#pragma unroll
    for (int i = 0; i < 16; i++) ereg[i] = 0.f;
    float asum_local = 0.f;
    int myk = tid >> 3, myd0 = tid & 7;

    for (int t = blockIdx.x; t < NN / 32; t += gridDim.x) {
        int n0 = t * 32;
#pragma unroll
        for (int r = 0; r < 4; r++) {
            int idx = r * 256 + tid;
            int n = idx >> 5, d4 = (idx & 31) * 4;
            float4 v = *(const float4*)(ZDt + ((long)b * NN + n0 + n) * DD + d4);
            xs[d4][n] = v.x; xs[d4 + 1][n] = v.y; xs[d4 + 2][n] = v.z; xs[d4 + 3][n] = v.w;
        }
        __syncthreads();
        for (int round = 0; round < 4; round++) {
            int n = round * 8 + wid;
            float xx = 0.f;
            for (int d = lane; d < DD; d += 32) { float x = xs[d][n]; xx += x * x; }
            for (int o = 16; o; o >>= 1) xx += __shfl_xor_sync(0xffffffffu, xx, o);
            float dot = 0.f;
#pragma unroll 8
            for (int d = 0; d < DD; d++) dot += xs[d][n] * cs[lane][d];
            float s = sc[lane] * (xx - 2.f * dot + cn[lane]);
            float mx = s;
            for (int o = 16; o; o >>= 1) mx = fmaxf(mx, __shfl_xor_sync(0xffffffffu, mx, o));
            float e = __expf(s - mx);
            float ssum = e;
            for (int o = 16; o; o >>= 1) ssum += __shfl_xor_sync(0xffffffffu, ssum, o);
            float a = e / ssum;
            Ash[wid][lane] = a;
            asum_local += a;
            __syncthreads();
#pragma unroll
            for (int nn2 = 0; nn2 < 8; nn2++) {
                float av = Ash[nn2][myk];
                int ncol = round * 8 + nn2;
#pragma unroll
                for (int i = 0; i < 16; i++)
                    ereg[i] += av * xs[myd0 + 8 * i][ncol];
            }
            __syncthreads();
        }
    }
#pragma unroll
    for (int i = 0; i < 16; i++)
        atomicAdd(&Eacc[((long)b * KK + myk) * DD + myd0 + 8 * i], ereg[i]);
    atomicAdd(&Asum[b * KK + lane], asum_local);
}

// ------------- BN over K + Es -------------
__global__ void bn_es_kernel(const float* __restrict__ Eacc, const float* __restrict__ Asum,
                             const float* __restrict__ codewords, float* __restrict__ Es)
{
    int k = blockIdx.x, tid = threadIdx.x;
    __shared__ double shs[256], shs2[256];
    float vals[4];
    double s = 0.0, s2 = 0.0;
#pragma unroll
    for (int i = 0; i < 4; i++) {
        int idx = tid + i * 256;
        int b = idx >> 7, d = idx & 127;
        float v = Eacc[((long)b * KK + k) * DD + d] - Asum[b * KK + k] * codewords[k * DD + d];
        vals[i] = v; s += v; s2 += (double)v * v;
    }
    shs[tid] = s; shs2[tid] = s2; __syncthreads();
    for (int o = 128; o; o >>= 1) {
        if (tid < o) { shs[tid] += shs[tid + o]; shs2[tid] += shs2[tid + o]; }
        __syncthreads();
    }
    double mean = shs[0] / 1024.0;
    double var = shs2[0] / 1024.0 - mean * mean;
    float inv = rsqrtf((float)var + 1e-5f);
    float mf = (float)mean;
#pragma unroll
    for (int i = 0; i < 4; i++) {
        int idx = tid + i * 256;
        int b = idx >> 7, d = idx & 127;
        float e = (vals[i] - mf) * inv;
        if (e > 0.f) atomicAdd(&Es[b * DD + d], e);
    }
}

// ------------- gamma = sigmoid(Es @ W_fc^T + b_fc) -------------
__global__ void gamma_kernel(const float* __restrict__ Es, const float* __restrict__ W_fc,
                             const float* __restrict__ b_fc, float* __restrict__ gam)
{
    int idx = blockIdx.x * blockDim.x + threadIdx.x;
    int b = idx / CIN, c = idx % CIN;
    float s = b_fc[c];
    for (int d = 0; d < DD; d++) s += Es[b * DD + d] * W_fc[c * DD + d];
    gam[idx] = 1.f / (1.f + expf(-s));
}

// ------------- launch -------------
#define GA(T, p, s) T* p; cudaGetSymbolAddress((void**)&p, s)

extern "C" void kernel_launch(void* const* d_in, const int* in_sizes, int n_in,
                              void* d_out, int out_size)
{
    const float* X        = (const float*)d_in[0];
    const float* W_theta  = (const float*)d_in[1];
    const float* b_theta  = (const float*)d_in[2];
    const float* W_phi    = (const float*)d_in[3];
    const float* b_phi    = (const float*)d_in[4];
    const float* W_g      = (const float*)d_in[5];
    const float* b_g      = (const float*)d_in[6];
    const float* W2       = (const float*)d_in[7];
    const float* b2       = (const float*)d_in[8];
    const float* W3       = (const float*)d_in[9];
    const float* b3       = (const float*)d_in[10];
    const float* codewords= (const float*)d_in[11];
    const float* scale    = (const float*)d_in[12];
    const float* W_fc     = (const float*)d_in[13];
    const float* b_fc     = (const float*)d_in[14];

    GA(bf16, Xh, g_Xh); GA(bf16, Xm, g_Xm);
    GA(bf16, Xch, g_Xch); GA(bf16, Xcm, g_Xcm); GA(bf16, Xcl, g_Xcl);
    GA(bf16, Wth, g_Wth); GA(bf16, Wtm, g_Wtm); GA(bf16, Wtl, g_Wtl);
    GA(bf16, Wph, g_Wph); GA(bf16, Wpm, g_Wpm); GA(bf16, Wpl, g_Wpl);
    GA(bf16, WgTh, g_WgTh); GA(bf16, WgTm, g_WgTm);
    GA(bf16, W2h, g_W2h); GA(bf16, W2m, g_W2m);
    GA(bf16, W3h, g_W3h); GA(bf16, W3m, g_W3m);
    GA(float, Gp, g_Gp);
    GA(bf16, GRh, g_GRh); GA(bf16, GRm, g_GRm); GA(bf16, GRl, g_GRl);
    GA(float, T1p, g_T1p);
    GA(bf16, T1h, g_T1h); GA(bf16, T1m, g_T1m); GA(bf16, T1l, g_T1l);
    GA(float, Fp4, g_Fp4);
    GA(bf16, Fh, g_Fh); GA(bf16, Fm, g_Fm);
    GA(bf16, Wfh, g_Wfh); GA(bf16, Wfm, g_Wfm);
    GA(float, Mf, g_Mf);
    GA(bf16, Mkh, g_Mkh); GA(bf16, Mkm, g_Mkm);
    GA(bf16, Mch, g_Mch); GA(bf16, Mcm, g_Mcm);
    GA(bf16, M2h, g_M2h); GA(bf16, M2m, g_M2m);
    GA(float, b2e, g_b2e); GA(float, b3e, g_b3e);
    GA(float, ZDt, g_ZDt);
    GA(float, Eacc, g_Eacc); GA(float, Asum, g_Asum);
    GA(float, Es, g_Es); GA(float, gamB, g_gam);

    const int SMEM6 = 2 * 6 * 8192;   // 98304 (2-stage x6)
    const int SMEM3 = 3 * 4 * 8192;   // 98304 (3-stage x3)
    cudaFuncSetAttribute((const void*)mma_gemm<6, false, 2>, cudaFuncAttributeMaxDynamicSharedMemorySize, SMEM6);
    cudaFuncSetAttribute((const void*)mma_gemm<6, true, 2>,  cudaFuncAttributeMaxDynamicSharedMemorySize, SMEM6);
    cudaFuncSetAttribute((const void*)mma_gemm<3, false, 3>, cudaFuncAttributeMaxDynamicSharedMemorySize, SMEM3);

    split_all<<<512, 256>>>(W_theta, W_phi, W_g, W2, W3);   // also zeroes accumulators
    tsplit2<<<dim3(288, 16, BB), dim3(32, 8)>>>(X);

    // Gram: G = X·X^T per batch, lower-triangle tiles, split-K=18 (KS=512)
    mma_gemm<6, true, 2><<<dim3(10, 1, BB * GS), 256, SMEM6>>>(
        Xch, Xcm, Xcl, NN, (long)CIN * NN, Xch, Xcm, Xcl, NN, (long)CIN * NN,
        Gp, nullptr, nullptr, CIN, (long)CIN * CIN,
        nullptr, 0, nullptr, 0, nullptr, 0, nullptr, 0, 16, GS);
    gram_reduce<<<8192, 256>>>();

    bcorr<<<16, 256>>>(W_theta, W_phi);

    // T1 = Wphi @ G (256x512/batch), x6, split-K=4 -> fp32 partials   [launch #6 for ncu]
    mma_gemm<6, false, 2><<<dim3(4, 2, BB * 4), 256, SMEM6>>>(
        Wph, Wpm, Wpl, CIN, 0, GRh, GRm, GRl, CIN, (long)CIN * CIN,
        T1p, nullptr, nullptr, CIN, 131072L,
        nullptr, 0, nullptr, 0, nullptr, 0, nullptr, 0, 4, 4);
    t1_reduce<<<4096, 256>>>();

    // f = Wtheta @ T1^T (256x256/batch), x6, split-K=4 -> fp32 partials
    mma_gemm<6, false, 2><<<dim3(2, 2, BB * 4), 256, SMEM6>>>(
        Wth, Wtm, Wtl, CIN, 0, T1h, T1m, T1l, CIN, 131072L,
        Fp4, nullptr, nullptr, C1, 65536L,
        nullptr, 0, nullptr, 0, nullptr, 0, nullptr, 0, 4, 4);

    softmaxT<<<BB * C1, 256>>>(b_theta, b_phi);

    // Wf = W2 @ f^T: (512 x 256)/batch, x3 -> h/m parts
    mma_gemm<3, false, 3><<<dim3(2, 4, BB), 256, SMEM3>>>(
        W2h, W2m, nullptr, C1, 0, Fh, Fm, nullptr, C1, 65536L,
        nullptr, Wfh, Wfm, C1, 131072L,
        nullptr, 0, nullptr, 0, nullptr, 0, nullptr, 0, 8, 1);

    b2e_kernel<<<16, 256>>>(b2, b_g);
    b3e_kernel<<<4, 256>>>(W3, b3);

    // M[k,cc] = Wg^T · Wf^T : A=WgT (k,d), B=Wf (cc,d), K=256, fp32 out
    mma_gemm<3, false, 3><<<dim3(4, 4, BB), 256, SMEM3>>>(
        WgTh, WgTm, nullptr, C1, 0, Wfh, Wfm, nullptr, C1, 131072L,
        Mf, nullptr, nullptr, CIN, 262144L,
        nullptr, 0, nullptr, 0, nullptr, 0, nullptr, 0, 8, 1);
    msplit<<<8192, 256>>>();

    // M2^T[d,k] = W3 · (M+I): A=W3 (d,c), B=Mk (k,c), K=512, +W3 residual -> h/m parts
    mma_gemm<3, false, 3><<<dim3(4, 1, BB), 256, SMEM3>>>(
        W3h, W3m, nullptr, CIN, 0, Mkh, Mkm, nullptr, CIN, 262144L,
        nullptr, M2h, M2m, CIN, 65536L,
        nullptr, 0, nullptr, 0, W3, 0, nullptr, 0, 16, 1);

    // z_ (n rows, d contig): C[n,d] = X_t·M2 + b3e[d] : A=X_t (n,k), B=M2^T (d,k), K=512
    mma_gemm<3, false, 3><<<dim3(1, 72, BB), 256, SMEM3>>>(
        Xh, Xm, nullptr, CIN, (long)NN * CIN, M2h, M2m, nullptr, CIN, 65536L,
        ZDt, nullptr, nullptr, DD, (long)NN * DD,
        b3e, DD, nullptr, 0, nullptr, 0, nullptr, 0, 16, 1);

    encode_kernel<<<dim3(96, BB), 256>>>(ZDt, codewords, scale, Eacc, Asum);
    bn_es_kernel<<<KK, 256>>>(Eacc, Asum, codewords, Es);
    gamma_kernel<<<(BB * CIN) / 256, 256>>>(Es, W_fc, b_fc, gamB);

    // out (B,C,N): C[cc,n] = ((M+I)^T·X_t^T + b2e[cc]) * gamma[cc]  -> d_out directly
    mma_gemm<3, false, 3><<<dim3(72, 4, BB), 256, SMEM3>>>(
        Mch, Mcm, nullptr, CIN, 262144L, Xh, Xm, nullptr, CIN, (long)NN * CIN,
        (float*)d_out, nullptr, nullptr, NN, (long)CIN * NN,
        nullptr, 0, b2e, CIN, nullptr, 0, gamB, CIN, 16, 1);
}

// round 14
// speedup vs baseline: 1.0683x; 1.0147x over previous
#include <cuda_runtime.h>
#include <cuda_bf16.h>
#include <math.h>
#include <stdint.h>

#define BB 8
#define CIN 512
#define C1 256
#define DD 128
#define KK 32
#define NN 9216
#define ROWS (BB*NN)
#define GS 18            // Gram split-K slices
typedef __nv_bfloat16 bf16;
typedef unsigned int u32;

// ------------- scratch (device globals) -------------
__device__ bf16 g_Xh[ROWS*CIN], g_Xm[ROWS*CIN];                      // X (N-major rows n, k contig)
__device__ bf16 g_Xch[ROWS*CIN], g_Xcm[ROWS*CIN], g_Xcl[ROWS*CIN];   // X (C-major rows ch, n contig)
__device__ bf16 g_Wth[C1*CIN], g_Wtm[C1*CIN], g_Wtl[C1*CIN];
__device__ bf16 g_Wph[C1*CIN], g_Wpm[C1*CIN], g_Wpl[C1*CIN];
__device__ bf16 g_WgTh[CIN*C1], g_WgTm[CIN*C1];                      // Wg^T (k rows, d contig)
__device__ bf16 g_W2h[CIN*C1], g_W2m[CIN*C1];
__device__ bf16 g_W3h[DD*CIN], g_W3m[DD*CIN];
__device__ float g_Gp[(BB*GS)*CIN*CIN];                              // Gram split-K partials
__device__ bf16 g_GRh[BB*CIN*CIN], g_GRm[BB*CIN*CIN], g_GRl[BB*CIN*CIN];
__device__ float g_T1p[BB*4*C1*CIN];                                 // T1 split-K partials
__device__ bf16 g_T1h[BB*C1*CIN], g_T1m[BB*C1*CIN], g_T1l[BB*C1*CIN];
__device__ float g_Fp4[BB*4*C1*C1];                                  // f split-K partials
__device__ bf16 g_Fh[BB*C1*C1], g_Fm[BB*C1*C1];                      // f^T parts (d rows, c contig)
__device__ bf16 g_Wfh[BB*CIN*C1], g_Wfm[BB*CIN*C1];                  // Wf = W2·f (cc rows, d contig)
__device__ float g_Mf[BB*CIN*CIN];                                   // M fp32 (k rows, cc contig)
__device__ bf16 g_Mkh[BB*CIN*CIN], g_Mkm[BB*CIN*CIN];                // M (k rows, cc contig)
__device__ bf16 g_Mch[BB*CIN*CIN], g_Mcm[BB*CIN*CIN];                // (M+I)^T (cc rows, k contig)
__device__ bf16 g_M2h[BB*DD*CIN], g_M2m[BB*DD*CIN];                  // M2^T (d rows, k contig)
__device__ float g_b2e[BB*CIN];                                      // b2 + Wf·bg
__device__ float g_b3e[BB*DD];                                       // W3·b2e + b3
__device__ float g_sx[BB*CIN];
__device__ float g_bth[BB*C1], g_bph[BB*C1];
__device__ float g_Eacc[BB*KK*DD], g_Asum[BB*KK], g_Es[BB*DD], g_gam[BB*CIN];

// ------------- helpers -------------
__device__ __forceinline__ u32 smem_u32(const void* p) {
    u32 a;
    asm("{ .reg .u64 t; cvta.to.shared.u64 t, %1; cvt.u32.u64 %0, t; }" : "=r"(a) : "l"(p));
    return a;
}
__device__ __forceinline__ void cp16(u32 d, const void* s) {
    asm volatile("cp.async.cg.shared.global [%0], [%1], 16;" :: "r"(d), "l"(s));
}
__device__ __forceinline__ void cp_commit() { asm volatile("cp.async.commit_group;" ::: "memory"); }
template<int N> __device__ __forceinline__ void cp_waitg() {
    asm volatile("cp.async.wait_group %0;" :: "n"(N) : "memory");
}
__device__ __forceinline__ void ldm_x4(u32* r, u32 addr) {
    asm volatile("ldmatrix.sync.aligned.m8n8.x4.shared.b16 {%0,%1,%2,%3}, [%4];"
        : "=r"(r[0]), "=r"(r[1]), "=r"(r[2]), "=r"(r[3]) : "r"(addr));
}
__device__ __forceinline__ void mma16816(float* d, const u32* a, const u32* b) {
    asm volatile(
        "mma.sync.aligned.m16n8k16.row.col.f32.bf16.bf16.f32 "
        "{%0,%1,%2,%3}, {%4,%5,%6,%7}, {%8,%9}, {%0,%1,%2,%3};"
        : "+f"(d[0]), "+f"(d[1]), "+f"(d[2]), "+f"(d[3])
        : "r"(a[0]), "r"(a[1]), "r"(a[2]), "r"(a[3]), "r"(b[0]), "r"(b[1]));
}
__device__ __forceinline__ void st2bf(bf16* p, long i, float a, float b_) {
    __nv_bfloat162 v(__float2bfloat16(a), __float2bfloat16(b_));
    *(u32*)(p + i) = *(u32*)&v;
}

// ============ mma.sync bf16-split GEMM, product-shared tiles, BK=32 ============
template<int NPROD, bool SYM, int NSTG>
__global__ __launch_bounds__(256, 2) void mma_gemm(
    const bf16* __restrict__ Ah, const bf16* __restrict__ Am, const bf16* __restrict__ Al,
    int lda, long sAb,
    const bf16* __restrict__ Bh, const bf16* __restrict__ Bm, const bf16* __restrict__ Bl,
    int ldb, long sBb,
    float* __restrict__ C, bf16* __restrict__ Ch, bf16* __restrict__ Cm,
    int ldc, long sCz,
    const float* __restrict__ biasC, long sBC,
    const float* __restrict__ biasR, long sBR,
    const float* __restrict__ Rf, long sRz,
    const float* __restrict__ scaleR, long sSR,
    int NCH, int S)
{
    constexpr int NA = (NPROD == 6) ? 3 : 2;
    constexpr int NB = NA;
    constexpr int STAGE = (NA + NB) * 8192;

    extern __shared__ __align__(16) char smem[];
    const u32 sbase = smem_u32(smem);

    const int tid = threadIdx.x, lane = tid & 31, wid = tid >> 5;
    const int wm = wid & 1, wn = wid >> 1;
    const int z = blockIdx.z, b = z / S, s = z % S;
    int bx, by;
    if (SYM) {
        int p = blockIdx.x;
        by = (p < 1) ? 0 : (p < 3) ? 1 : (p < 6) ? 2 : 3;
        bx = p - (by * (by + 1)) / 2;
    } else { bx = blockIdx.x; by = blockIdx.y; }
    const long m0 = (long)by * 128;
    const int n0 = bx * 128;
    const int KS = NCH * 32;

    const long abase = (long)b * sAb + m0 * lda + (long)s * KS;
    const long bbase = (long)b * sBb + (long)n0 * ldb + (long)s * KS;

    const bf16* APT[3] = {Ah, Am, Al};
    const bf16* BPT[3] = {Bh, Bm, Bl};

    float acc[4][4][4];
#pragma unroll
    for (int i = 0; i < 4; i++)
#pragma unroll
        for (int j = 0; j < 4; j++)
#pragma unroll
            for (int r = 0; r < 4; r++) acc[i][j][r] = 0.f;

    const int row2 = tid >> 1, lq = tid & 1;
    const int sw = (row2 >> 1) & 3;
    const u32 c0off = (u32)(row2 * 64 + (((lq * 2 + 0) ^ sw) << 4));
    const u32 c1off = (u32)(row2 * 64 + (((lq * 2 + 1) ^ sw) << 4));

    auto issue = [&](int c) {
        int k0 = c * 32;
        u32 sd = sbase + (c % NSTG) * STAGE;
#pragma unroll
        for (int p = 0; p < NA; p++) {
            const bf16* ap = APT[p] + abase + k0 + (long)row2 * lda + lq * 16;
            cp16(sd + p * 8192 + c0off, ap);
            cp16(sd + p * 8192 + c1off, ap + 8);
        }
#pragma unroll
        for (int p = 0; p < NB; p++) {
            const bf16* bp = BPT[p] + bbase + k0 + (long)row2 * ldb + lq * 16;
            cp16(sd + (NA + p) * 8192 + c0off, bp);
            cp16(sd + (NA + p) * 8192 + c1off, bp + 8);
        }
        cp_commit();
    };

    u32 aoff[4], boff[2];
#pragma unroll
    for (int t = 0; t < 4; t++) {
        int ra = wm * 64 + t * 16 + (lane & 15);
        int j = lane >> 4;
        aoff[t] = (u32)(ra * 64 + ((j ^ ((ra >> 1) & 3)) << 4));
    }
#pragma unroll
    for (int u = 0; u < 2; u++) {
        int rb = wn * 32 + u * 16 + (lane & 7) + ((lane >> 4) & 1) * 8;
        int j = (lane >> 3) & 1;
        boff[u] = (u32)(rb * 64 + ((j ^ ((rb >> 1) & 3)) << 4));
    }

#pragma unroll
    for (int p = 0; p < NSTG - 1; p++) if (p < NCH) issue(p);

    for (int c = 0; c < NCH; c++) {
        if (c + NSTG - 1 < NCH) { issue(c + NSTG - 1); cp_waitg<NSTG - 1>(); }
        else if (NSTG == 3 && c + 1 < NCH) cp_waitg<1>();
        else cp_waitg<0>();
        __syncthreads();
        u32 sA = sbase + (c % NSTG) * STAGE;
        u32 sB = sA + NA * 8192;
#pragma unroll
        for (int kk = 0; kk < 2; kk++) {
            u32 kx = kk << 5;
            u32 bfr[NB][2][4];
#pragma unroll
            for (int pb = 0; pb < NB; pb++)
#pragma unroll
                for (int u = 0; u < 2; u++)
                    ldm_x4(bfr[pb][u], sB + pb * 8192 + (boff[u] ^ kx));
#pragma unroll
            for (int pa = 0; pa < NA; pa++) {
                u32 af[4][4];
#pragma unroll
                for (int t = 0; t < 4; t++)
                    ldm_x4(af[t], sA + pa * 8192 + (aoff[t] ^ kx));
#pragma unroll
                for (int pb = 0; pb < NB; pb++) {
                    if (pa + pb < NB) {
#pragma unroll
                        for (int mi = 0; mi < 4; mi++)
#pragma unroll
                            for (int ni = 0; ni < 4; ni++)
                                mma16816(acc[mi][ni], af[mi], &bfr[pb][ni >> 1][(ni & 1) * 2]);
                    }
                }
            }
        }
        __syncthreads();
    }

    // ---- epilogue ----
    const int mrow = lane >> 2, nc2 = (lane & 3) * 2;
#pragma unroll
    for (int mi = 0; mi < 4; mi++) {
#pragma unroll
        for (int rp = 0; rp < 2; rp++) {
            long row = m0 + wm * 64 + mi * 16 + mrow + rp * 8;
            long coff = (long)z * sCz + row * ldc;
            long roff = (long)b * sRz + row * ldc;
            float br = biasR ? biasR[b * sBR + row] : 0.f;
            float sr = scaleR ? scaleR[b * sSR + row] : 1.f;
#pragma unroll
            for (int ni = 0; ni < 4; ni++) {
                int col = n0 + wn * 32 + ni * 8 + nc2;
                float v0 = acc[mi][ni][rp * 2 + 0] + br;
                float v1 = acc[mi][ni][rp * 2 + 1] + br;
                if (biasC) { v0 += biasC[b * sBC + col]; v1 += biasC[b * sBC + col + 1]; }
                if (Rf) {
                    float2 r = *(const float2*)&Rf[roff + col];
                    v0 += r.x; v1 += r.y;
                }
                v0 *= sr; v1 *= sr;
                if (C) *(float2*)&C[coff + col] = make_float2(v0, v1);
                if (Ch) {
                    float h0 = __bfloat162float(__float2bfloat16(v0));
                    float h1 = __bfloat162float(__float2bfloat16(v1));
                    st2bf(Ch, coff + col, v0, v1);
                    st2bf(Cm, coff + col, v0 - h0, v1 - h1);
                }
            }
        }
    }
}

// ============ fused z_ GEMM + Deep-TEN encode ============
// Tile: 128 rows (n) x 128 cols (d) = z_ = Xt·M2 + b3e; then encode in-kernel.
// smem: 3-stage ring (96KB) overlaid after mainloop by zs[128][129] + cs[32][129] + cn/sc/Ash.
__global__ __launch_bounds__(256, 2) void zde_kernel(
    const bf16* __restrict__ Ah, const bf16* __restrict__ Am,
    const bf16* __restrict__ Bh, const bf16* __restrict__ Bm,
    const float* __restrict__ b3e,
    const float* __restrict__ codewords, const float* __restrict__ scale,
    float* __restrict__ Eacc, float* __restrict__ Asum)
{
    constexpr int STAGE = 32768;
    extern __shared__ __align__(16) char smem[];
    const u32 sbase = smem_u32(smem);
    float* zs = (float*)smem;                    // [128][129] = 66048 B
    float* cs = (float*)(smem + 66048);          // [32][129]  = 16512 B
    float* cn = (float*)(smem + 82560);          // [32]
    float* sc = cn + 32;                         // [32]
    float* Ash = sc + 32;                        // [8][32]

    const int tid = threadIdx.x, lane = tid & 31, wid = tid >> 5;
    const int wm = wid & 1, wn = wid >> 1;
    const int b = blockIdx.y;
    const long m0 = (long)blockIdx.x * 128;

    const long abase = (long)b * NN * CIN + m0 * CIN;
    const long bbase = (long)b * (DD * CIN);

    float acc[4][4][4];
#pragma unroll
    for (int i = 0; i < 4; i++)
#pragma unroll
        for (int j = 0; j < 4; j++)
#pragma unroll
            for (int r = 0; r < 4; r++) acc[i][j][r] = 0.f;

    const int row2 = tid >> 1, lq = tid & 1;
    const int sw2 = (row2 >> 1) & 3;
    const u32 c0off = (u32)(row2 * 64 + (((lq * 2 + 0) ^ sw2) << 4));
    const u32 c1off = (u32)(row2 * 64 + (((lq * 2 + 1) ^ sw2) << 4));

    auto issue = [&](int c) {
        int k0 = c * 32;
        u32 sd = sbase + (c % 3) * STAGE;
        const bf16* a0 = Ah + abase + k0 + (long)row2 * CIN + lq * 16;
        const bf16* a1 = Am + abase + k0 + (long)row2 * CIN + lq * 16;
        cp16(sd + c0off, a0);            cp16(sd + c1off, a0 + 8);
        cp16(sd + 8192 + c0off, a1);     cp16(sd + 8192 + c1off, a1 + 8);
        const bf16* b0 = Bh + bbase + k0 + (long)row2 * CIN + lq * 16;
        const bf16* b1 = Bm + bbase + k0 + (long)row2 * CIN + lq * 16;
        cp16(sd + 16384 + c0off, b0);    cp16(sd + 16384 + c1off, b0 + 8);
        cp16(sd + 24576 + c0off, b1);    cp16(sd + 24576 + c1off, b1 + 8);
        cp_commit();
    };

    u32 aoff[4], boff[2];
#pragma unroll
    for (int t = 0; t < 4; t++) {
        int ra = wm * 64 + t * 16 + (lane & 15);
        int j = lane >> 4;
        aoff[t] = (u32)(ra * 64 + ((j ^ ((ra >> 1) & 3)) << 4));
    }
#pragma unroll
    for (int u = 0; u < 2; u++) {
        int rb = wn * 32 + u * 16 + (lane & 7) + ((lane >> 4) & 1) * 8;
        int j = (lane >> 3) & 1;
        boff[u] = (u32)(rb * 64 + ((j ^ ((rb >> 1) & 3)) << 4));
    }

    issue(0); issue(1);
    for (int c = 0; c < 16; c++) {
        if (c + 2 < 16) { issue(c + 2); cp_waitg<2>(); }
        else if (c + 1 < 16) cp_waitg<1>();
        else cp_waitg<0>();
        __syncthreads();
        u32 sA = sbase + (c % 3) * STAGE;
        u32 sB = sA + 16384;
#pragma unroll
        for (int kk = 0; kk < 2; kk++) {
            u32 kx = kk << 5;
            u32 bfr[2][2][4];
#pragma unroll
            for (int pb = 0; pb < 2; pb++)
#pragma unroll
                for (int u = 0; u < 2; u++)
                    ldm_x4(bfr[pb][u], sB + pb * 8192 + (boff[u] ^ kx));
#pragma unroll
            for (int pa = 0; pa < 2; pa++) {
                u32 af[4][4];
#pragma unroll
                for (int t = 0; t < 4; t++)
                    ldm_x4(af[t], sA + pa * 8192 + (aoff[t] ^ kx));
#pragma unroll
                for (int pb = 0; pb < 2; pb++) {
                    if (pa + pb < 2) {
#pragma unroll
                        for (int mi = 0; mi < 4; mi++)
#pragma unroll
                            for (int ni = 0; ni < 4; ni++)
                                mma16816(acc[mi][ni], af[mi], &bfr[pb][ni >> 1][(ni & 1) * 2]);
                    }
                }
            }
        }
        __syncthreads();
    }

    // ---- stage z_ tile into smem (overlaying the ring; safe after last sync) ----
    const int mrow = lane >> 2, nc2 = (lane & 3) * 2;
#pragma unroll
    for (int mi = 0; mi < 4; mi++) {
#pragma unroll
        for (int rp = 0; rp < 2; rp++) {
            int row = wm * 64 + mi * 16 + mrow + rp * 8;
#pragma unroll
            for (int ni = 0; ni < 4; ni++) {
                int col = wn * 32 + ni * 8 + nc2;
                zs[row * 129 + col]     = acc[mi][ni][rp * 2 + 0] + b3e[b * DD + col];
                zs[row * 129 + col + 1] = acc[mi][ni][rp * 2 + 1] + b3e[b * DD + col + 1];
            }
        }
    }
    // codewords etc
    for (int i = tid; i < KK * DD; i += 256) cs[(i >> 7) * 129 + (i & 127)] = codewords[i];
    if (tid < KK) sc[tid] = scale[tid];
    __syncthreads();
    if (tid < KK) {
        float s = 0.f;
        for (int d = 0; d < DD; d++) { float c = cs[tid * 129 + d]; s += c * c; }
        cn[tid] = s;
    }
    __syncthreads();

    // ---- encode: identical math to the standalone kernel ----
    float ereg[16];
#pragma unroll
    for (int i = 0; i < 16; i++) ereg[i] = 0.f;
    float asum_local = 0.f;
    int myk = tid >> 3, myd0 = tid & 7;

    for (int round = 0; round < 16; round++) {
        int n = round * 8 + wid;
        float xx = 0.f;
        for (int d = lane; d < DD; d += 32) { float x = zs[n * 129 + d]; xx += x * x; }
        for (int o = 16; o; o >>= 1) xx += __shfl_xor_sync(0xffffffffu, xx, o);
        float dot = 0.f;
#pragma unroll 8
        for (int d = 0; d < DD; d++) dot += zs[n * 129 + d] * cs[lane * 129 + d];
        float s = sc[lane] * (xx - 2.f * dot + cn[lane]);
        float mx = s;
        for (int o = 16; o; o >>= 1) mx = fmaxf(mx, __shfl_xor_sync(0xffffffffu, mx, o));
        float e = __expf(s - mx);
        float ssum = e;
        for (int o = 16; o; o >>= 1) ssum += __shfl_xor_sync(0xffffffffu, ssum, o);
        float a = e / ssum;
        Ash[wid * 32 + lane] = a;
        asum_local += a;
        __syncthreads();
#pragma unroll
        for (int nn2 = 0; nn2 < 8; nn2++) {
            float av = Ash[nn2 * 32 + myk];
            int ncol = round * 8 + nn2;
#pragma unroll
            for (int i = 0; i < 16; i++)
                ereg[i] += av * zs[ncol * 129 + myd0 + 8 * i];
        }
        __syncthreads();
    }
#pragma unroll
    for (int i = 0; i < 16; i++)
        atomicAdd(&Eacc[((long)b * KK + myk) * DD + myd0 + 8 * i], ereg[i]);
    atomicAdd(&Asum[b * KK + lane], asum_local);
}

// ------------- X: transpose+split (N-major h/m) AND straight split (C-major h/m/l) + row sums -------------
__global__ void tsplit2(const float* __restrict__ src)
{
    __shared__ float ts[32][33];
    int b = blockIdx.z;
    long o = (long)b * CIN * NN;
    int c0 = blockIdx.x * 32, r0 = blockIdx.y * 32;
    int tx = threadIdx.x, ty = threadIdx.y;
#pragma unroll
    for (int i = 0; i < 4; i++) {
        int ch = r0 + ty + i * 8;
        long sidx = o + (long)ch * NN + c0 + tx;
        float v = src[sidx];
        ts[ty + i * 8][tx] = v;
        bf16 hh = __float2bfloat16(v);
        float r1 = v - __bfloat162float(hh);
        bf16 mm = __float2bfloat16(r1);
        g_Xch[sidx] = hh; g_Xcm[sidx] = mm;
        g_Xcl[sidx] = __float2bfloat16(r1 - __bfloat162float(mm));
        float sum = v;
#pragma unroll
        for (int off = 16; off; off >>= 1) sum += __shfl_xor_sync(0xffffffffu, sum, off);
        if (tx == 0) atomicAdd(&g_sx[b * CIN + ch], sum);
    }
    __syncthreads();
#pragma unroll
    for (int i = 0; i < 4; i++) {
        int n = c0 + ty + i * 8;
        float v = ts[tx][ty + i * 8];
        long tdx = (long)b * NN * CIN + (long)n * CIN + (r0 + tx);
        bf16 hh = __float2bfloat16(v);
        g_Xh[tdx] = hh;
        g_Xm[tdx] = __float2bfloat16(v - __bfloat162float(hh));
    }
}

// ------------- weight splits + accumulator zeroing -------------
__global__ void split_all(const float* __restrict__ Wt, const float* __restrict__ Wp,
                          const float* __restrict__ Wg, const float* __restrict__ W2,
                          const float* __restrict__ W3)
{
    int i = blockIdx.x * 256 + threadIdx.x;
    if (i < BB * KK * DD) g_Eacc[i] = 0.f;
    if (i < BB * KK)      g_Asum[i] = 0.f;
    if (i < BB * DD)      g_Es[i]   = 0.f;
    if (i < BB * CIN)     g_sx[i]   = 0.f;
    if (i < C1 * CIN) {
        float v = Wt[i];
        bf16 h = __float2bfloat16(v); float r1 = v - __bfloat162float(h);
        bf16 m = __float2bfloat16(r1);
        g_Wth[i] = h; g_Wtm[i] = m; g_Wtl[i] = __float2bfloat16(r1 - __bfloat162float(m));
        v = Wp[i];
        h = __float2bfloat16(v); r1 = v - __bfloat162float(h);
        m = __float2bfloat16(r1);
        g_Wph[i] = h; g_Wpm[i] = m; g_Wpl[i] = __float2bfloat16(r1 - __bfloat162float(m));
        v = Wg[i];
        int d = i >> 9, k = i & 511;
        h = __float2bfloat16(v);
        g_WgTh[k * C1 + d] = h;
        g_WgTm[k * C1 + d] = __float2bfloat16(v - __bfloat162float(h));
        v = W2[i];
        h = __float2bfloat16(v);
        g_W2h[i] = h; g_W2m[i] = __float2bfloat16(v - __bfloat162float(h));
    }
    if (i < DD * CIN) {
        float v = W3[i];
        bf16 h = __float2bfloat16(v);
        g_W3h[i] = h; g_W3m[i] = __float2bfloat16(v - __bfloat162float(h));
    }
}

// ------------- reduce Gram split-K partials (triangle-only reads, mirror writes) -------------
__global__ void gram_reduce()
{
    long idx = (long)blockIdx.x * 256 + threadIdx.x;
    int b = (int)(idx >> 18);
    int rem = (int)(idx & 262143);
    int c1 = rem >> 9, c2 = rem & 511;
    int t1 = c1 >> 7, t2 = c2 >> 7;
    if (t1 < t2) return;
    float v = 0.f;
#pragma unroll
    for (int s = 0; s < GS; s++) v += g_Gp[(((long)(b * GS + s)) << 18) + (long)rem];
    bf16 h = __float2bfloat16(v);
    float r1 = v - __bfloat162float(h);
    bf16 m = __float2bfloat16(r1);
    bf16 l = __float2bfloat16(r1 - __bfloat162float(m));
    g_GRh[idx] = h; g_GRm[idx] = m; g_GRl[idx] = l;
    if (t1 > t2) {
        long mdx = (((long)b) << 18) + ((long)c2 << 9) + c1;
        g_GRh[mdx] = h; g_GRm[mdx] = m; g_GRl[mdx] = l;
    }
}

// ------------- reduce T1 split-K partials + 3-way split -------------
__global__ void t1_reduce()
{
    long idx = (long)blockIdx.x * 256 + threadIdx.x;
    int b = (int)(idx >> 17);
    long il = idx & 131071;
    float v = 0.f;
#pragma unroll
    for (int s = 0; s < 4; s++) v += g_T1p[(((long)(b * 4 + s)) << 17) + il];
    bf16 h = __float2bfloat16(v);
    float r1 = v - __bfloat162float(h);
    bf16 m = __float2bfloat16(r1);
    g_T1h[idx] = h; g_T1m[idx] = m;
    g_T1l[idx] = __float2bfloat16(r1 - __bfloat162float(m));
}

// ------------- M split: Mk = M (k rows), Mc = (M+I)^T (cc rows) -------------
__global__ void msplit()
{
    long idx = (long)blockIdx.x * 256 + threadIdx.x;
    int b = (int)(idx >> 18);
    int rem = (int)(idx & 262143);
    int k = rem >> 9, cc = rem & 511;
    float v = g_Mf[idx];
    bf16 h = __float2bfloat16(v);
    bf16 m = __float2bfloat16(v - __bfloat162float(h));
    g_Mkh[idx] = h; g_Mkm[idx] = m;
    float v2 = v + (k == cc ? 1.f : 0.f);
    bf16 h2 = __float2bfloat16(v2);
    bf16 m2 = __float2bfloat16(v2 - __bfloat162float(h2));
    long tdx = (((long)b) << 18) + ((long)cc << 9) + k;
    g_Mch[tdx] = h2; g_Mcm[tdx] = m2;
}

// ------------- bias rank-1 corrections -------------
__global__ void bcorr(const float* __restrict__ Wt, const float* __restrict__ Wp)
{
    int idx = blockIdx.x * 256 + threadIdx.x;
    int which = idx >> 11;
    int r = idx & 2047;
    int b = r >> 8, c = r & 255;
    const float* W = which ? Wp : Wt;
    float s = 0.f;
    for (int k = 0; k < CIN; k++) s += W[c * CIN + k] * g_sx[b * CIN + k];
    (which ? g_bph : g_bth)[b * C1 + c] = s;
}

// ------------- b2e = b2 + Wf·bg -------------
__global__ void b2e_kernel(const float* __restrict__ b2, const float* __restrict__ bg)
{
    int idx = blockIdx.x * 256 + threadIdx.x;
    int b = idx >> 9, c = idx & 511;
    float s = b2[c];
    long base = ((long)b << 17) + (long)c * C1;
    for (int d = 0; d < C1; d++)
        s += bg[d] * (__bfloat162float(g_Wfh[base + d]) + __bfloat162float(g_Wfm[base + d]));
    g_b2e[idx] = s;
}

// ------------- b3e = W3·b2e + b3 -------------
__global__ void b3e_kernel(const float* __restrict__ W3, const float* __restrict__ b3)
{
    int idx = blockIdx.x * 256 + threadIdx.x;
    int b = idx >> 7, d = idx & 127;
    float s = b3[d];
    for (int c = 0; c < CIN; c++) s += g_b2e[b * CIN + c] * W3[d * CIN + c];
    g_b3e[idx] = s;
}

// ------------- softmax over f rows, f^T bf16 out -------------
__global__ void softmaxT(const float* __restrict__ bth_bias, const float* __restrict__ bph_bias)
{
    int row = blockIdx.x, t = threadIdx.x;
    int b = row >> 8, c = row & 255;
    long il = (long)c * 256 + t;
    float v = 0.f;
#pragma unroll
    for (int s = 0; s < 4; s++) v += g_Fp4[(((long)(b * 4 + s)) << 16) + il];
    v += bth_bias[c] * g_bph[b * C1 + t]
       + bph_bias[t] * g_bth[b * C1 + c]
       + (float)NN * bth_bias[c] * bph_bias[t];
    __shared__ float sh[256];
    sh[t] = v; __syncthreads();
    for (int o = 128; o; o >>= 1) { if (t < o) sh[t] = fmaxf(sh[t], sh[t + o]); __syncthreads(); }
    float mx = sh[0]; __syncthreads();
    float e = expf(v - mx);
    sh[t] = e; __syncthreads();
    for (int o = 128; o; o >>= 1) { if (t < o) sh[t] += sh[t + o]; __syncthreads(); }
    float r = e / sh[0];
    long o2 = ((long)b << 16) + (long)t * 256 + c;
    bf16 h = __float2bfloat16(r);
    g_Fh[o2] = h;
    g_Fm[o2] = __float2bfloat16(r - __bfloat162float(h));
}

// ------------- BN over K + Es -------------
__global__ void bn_es_kernel(const float* __restrict__ Eacc, const float* __restrict__ Asum,
                             const float* __restrict__ codewords, float* __restrict__ Es)
{
    int k = blockIdx.x, tid = threadIdx.x;
    __shared__ double shs[256], shs2[256];
    float vals[4];
    double s = 0.0, s2 = 0.0;
#pragma unroll
    for (int i = 0; i < 4; i++) {
        int idx = tid + i * 256;
        int b = idx >> 7, d = idx & 127;
        float v = Eacc[((long)b * KK + k) * DD + d] - Asum[b * KK + k] * codewords[k * DD + d];
        vals[i] = v; s += v; s2 += (double)v * v;
    }
    shs[tid] = s; shs2[tid] = s2; __syncthreads();
    for (int o = 128; o; o >>= 1) {
        if (tid < o) { shs[tid] += shs[tid + o]; shs2[tid] += shs2[tid + o]; }
        __syncthreads();
    }
    double mean = shs[0] / 1024.0;
    double var = shs2[0] / 1024.0 - mean * mean;
    float inv = rsqrtf((float)var + 1e-5f);
    float mf = (float)mean;
#pragma unroll
    for (int i = 0; i < 4; i++) {
        int idx = tid + i * 256;
        int b = idx >> 7, d = idx & 127;
        float e = (vals[i] - mf) * inv;
        if (e > 0.f) atomicAdd(&Es[b * DD + d], e);
    }
}

// ------------- gamma = sigmoid(Es @ W_fc^T + b_fc) -------------
__global__ void gamma_kernel(const float* __restrict__ Es, const float* __restrict__ W_fc,
                             const float* __restrict__ b_fc, float* __restrict__ gam)
{
    int idx = blockIdx.x * blockDim.x + threadIdx.x;
    int b = idx / CIN, c = idx % CIN;
    float s = b_fc[c];
    for (int d = 0; d < DD; d++) s += Es[b * DD + d] * W_fc[c * DD + d];
    gam[idx] = 1.f / (1.f + expf(-s));
}

// ------------- launch -------------
#define GA(T, p, s) T* p; cudaGetSymbolAddress((void**)&p, s)

extern "C" void kernel_launch(void* const* d_in, const int* in_sizes, int n_in,
                              void* d_out, int out_size)
{
    const float* X        = (const float*)d_in[0];
    const float* W_theta  = (const float*)d_in[1];
    const float* b_theta  = (const float*)d_in[2];
    const float* W_phi    = (const float*)d_in[3];
    const float* b_phi    = (const float*)d_in[4];
    const float* W_g      = (const float*)d_in[5];
    const float* b_g      = (const float*)d_in[6];
    const float* W2       = (const float*)d_in[7];
    const float* b2       = (const float*)d_in[8];
    const float* W3       = (const float*)d_in[9];
    const float* b3       = (const float*)d_in[10];
    const float* codewords= (const float*)d_in[11];
    const float* scale    = (const float*)d_in[12];
    const float* W_fc     = (const float*)d_in[13];
    const float* b_fc     = (const float*)d_in[14];

    GA(bf16, Xh, g_Xh); GA(bf16, Xm, g_Xm);
    GA(bf16, Xch, g_Xch); GA(bf16, Xcm, g_Xcm); GA(bf16, Xcl, g_Xcl);
    GA(bf16, Wth, g_Wth); GA(bf16, Wtm, g_Wtm); GA(bf16, Wtl, g_Wtl);
    GA(bf16, Wph, g_Wph); GA(bf16, Wpm, g_Wpm); GA(bf16, Wpl, g_Wpl);
    GA(bf16, WgTh, g_WgTh); GA(bf16, WgTm, g_WgTm);
    GA(bf16, W2h, g_W2h); GA(bf16, W2m, g_W2m);
    GA(bf16, W3h, g_W3h); GA(bf16, W3m, g_W3m);
    GA(float, Gp, g_Gp);
    GA(bf16, GRh, g_GRh); GA(bf16, GRm, g_GRm); GA(bf16, GRl, g_GRl);
    GA(float, T1p, g_T1p);
    GA(bf16, T1h, g_T1h); GA(bf16, T1m, g_T1m); GA(bf16, T1l, g_T1l);
    GA(float, Fp4, g_Fp4);
    GA(bf16, Fh, g_Fh); GA(bf16, Fm, g_Fm);
    GA(bf16, Wfh, g_Wfh); GA(bf16, Wfm, g_Wfm);
    GA(float, Mf, g_Mf);
    GA(bf16, Mkh, g_Mkh); GA(bf16, Mkm, g_Mkm);
    GA(bf16, Mch, g_Mch); GA(bf16, Mcm, g_Mcm);
    GA(bf16, M2h, g_M2h); GA(bf16, M2m, g_M2m);
    GA(float, b2e, g_b2e); GA(float, b3e, g_b3e);
    GA(float, Eacc, g_Eacc); GA(float, Asum, g_Asum);
    GA(float, Es, g_Es); GA(float, gamB, g_gam);

    const int SMEM6 = 2 * 6 * 8192;   // 98304 (2-stage x6)
    const int SMEM3 = 3 * 4 * 8192;   // 98304 (3-stage x3)
    cudaFuncSetAttribute((const void*)mma_gemm<6, false, 2>, cudaFuncAttributeMaxDynamicSharedMemorySize, SMEM6);
    cudaFuncSetAttribute((const void*)mma_gemm<6, true, 2>,  cudaFuncAttributeMaxDynamicSharedMemorySize, SMEM6);
    cudaFuncSetAttribute((const void*)mma_gemm<3, false, 3>, cudaFuncAttributeMaxDynamicSharedMemorySize, SMEM3);
    cudaFuncSetAttribute((const void*)zde_kernel, cudaFuncAttributeMaxDynamicSharedMemorySize, SMEM3);

    split_all<<<512, 256>>>(W_theta, W_phi, W_g, W2, W3);
    tsplit2<<<dim3(288, 16, BB), dim3(32, 8)>>>(X);

    // Gram: G = X·X^T per batch, lower-triangle tiles, split-K=18 (KS=512)
    mma_gemm<6, true, 2><<<dim3(10, 1, BB * GS), 256, SMEM6>>>(
        Xch, Xcm, Xcl, NN, (long)CIN * NN, Xch, Xcm, Xcl, NN, (long)CIN * NN,
        Gp, nullptr, nullptr, CIN, (long)CIN * CIN,
        nullptr, 0, nullptr, 0, nullptr, 0, nullptr, 0, 16, GS);
    gram_reduce<<<8192, 256>>>();

    bcorr<<<16, 256>>>(W_theta, W_phi);

    // T1 = Wphi @ G (256x512/batch), x6, split-K=4
    mma_gemm<6, false, 2><<<dim3(4, 2, BB * 4), 256, SMEM6>>>(
        Wph, Wpm, Wpl, CIN, 0, GRh, GRm, GRl, CIN, (long)CIN * CIN,
        T1p, nullptr, nullptr, CIN, 131072L,
        nullptr, 0, nullptr, 0, nullptr, 0, nullptr, 0, 4, 4);
    t1_reduce<<<4096, 256>>>();

    // f = Wtheta @ T1^T (256x256/batch), x6, split-K=4
    mma_gemm<6, false, 2><<<dim3(2, 2, BB * 4), 256, SMEM6>>>(
        Wth, Wtm, Wtl, CIN, 0, T1h, T1m, T1l, CIN, 131072L,
        Fp4, nullptr, nullptr, C1, 65536L,
        nullptr, 0, nullptr, 0, nullptr, 0, nullptr, 0, 4, 4);

    softmaxT<<<BB * C1, 256>>>(b_theta, b_phi);

    // Wf = W2 @ f^T
    mma_gemm<3, false, 3><<<dim3(2, 4, BB), 256, SMEM3>>>(
        W2h, W2m, nullptr, C1, 0, Fh, Fm, nullptr, C1, 65536L,
        nullptr, Wfh, Wfm, C1, 131072L,
        nullptr, 0, nullptr, 0, nullptr, 0, nullptr, 0, 8, 1);

    b2e_kernel<<<16, 256>>>(b2, b_g);
    b3e_kernel<<<4, 256>>>(W3, b3);

    // M[k,cc] = Wg^T · Wf^T
    mma_gemm<3, false, 3><<<dim3(4, 4, BB), 256, SMEM3>>>(
        WgTh, WgTm, nullptr, C1, 0, Wfh, Wfm, nullptr, C1, 131072L,
        Mf, nullptr, nullptr, CIN, 262144L,
        nullptr, 0, nullptr, 0, nullptr, 0, nullptr, 0, 8, 1);
    msplit<<<8192, 256>>>();

    // M2^T[d,k] = W3 · (M+I)
    mma_gemm<3, false, 3><<<dim3(4, 1, BB), 256, SMEM3>>>(
        W3h, W3m, nullptr, CIN, 0, Mkh, Mkm, nullptr, CIN, 262144L,
        nullptr, M2h, M2m, CIN, 65536L,
        nullptr, 0, nullptr, 0, W3, 0, nullptr, 0, 16, 1);

    // fused z_ + encode
    zde_kernel<<<dim3(72, BB), 256, SMEM3>>>(
        Xh, Xm, M2h, M2m, b3e, codewords, scale, Eacc, Asum);

    bn_es_kernel<<<KK, 256>>>(Eacc, Asum, codewords, Es);
    gamma_kernel<<<(BB * CIN) / 256, 256>>>(Es, W_fc, b_fc, gamB);

    // out (B,C,N): C[cc,n] = ((M+I)^T·X_t^T + b2e[cc]) * gamma[cc]  -> d_out directly
    mma_gemm<3, false, 3><<<dim3(72, 4, BB), 256, SMEM3>>>(
        Mch, Mcm, nullptr, CIN, 262144L, Xh, Xm, nullptr, CIN, (long)NN * CIN,
        (float*)d_out, nullptr, nullptr, NN, (long)CIN * NN,
        nullptr, 0, b2e, CIN, nullptr, 0, gamB, CIN, 16, 1);
}

// round 16
// speedup vs baseline: 1.3057x; 1.2222x over previous
#include <cuda_runtime.h>
#include <cuda_bf16.h>
#include <math.h>
#include <stdint.h>

#define BB 8
#define CIN 512
#define C1 256
#define DD 128
#define KK 32
#define NN 9216
#define ROWS (BB*NN)
#define GS 18            // Gram split-K slices
typedef __nv_bfloat16 bf16;
typedef unsigned int u32;

// ------------- scratch (device globals) -------------
__device__ bf16 g_Xch[ROWS*CIN], g_Xcm[ROWS*CIN], g_Xcl[ROWS*CIN];   // X (C-major rows ch, n contig)
__device__ bf16 g_Wth[C1*CIN], g_Wtm[C1*CIN], g_Wtl[C1*CIN];
__device__ bf16 g_Wph[C1*CIN], g_Wpm[C1*CIN], g_Wpl[C1*CIN];
__device__ bf16 g_WgTh[CIN*C1], g_WgTm[CIN*C1];                      // Wg^T (k rows, d contig)
__device__ bf16 g_W2h[CIN*C1], g_W2m[CIN*C1];
__device__ bf16 g_W3h[DD*CIN], g_W3m[DD*CIN];
__device__ float g_Gp[(BB*GS)*CIN*CIN];                              // Gram split-K partials
__device__ bf16 g_GRh[BB*CIN*CIN], g_GRm[BB*CIN*CIN], g_GRl[BB*CIN*CIN];
__device__ float g_T1p[BB*4*C1*CIN];                                 // T1 split-K partials
__device__ bf16 g_T1h[BB*C1*CIN], g_T1m[BB*C1*CIN], g_T1l[BB*C1*CIN];
__device__ float g_Fp4[BB*4*C1*C1];                                  // f split-K partials
__device__ bf16 g_Fh[BB*C1*C1], g_Fm[BB*C1*C1];                      // f^T parts (d rows, c contig)
__device__ bf16 g_Wfh[BB*CIN*C1], g_Wfm[BB*CIN*C1];                  // Wf = W2·f (cc rows, d contig)
__device__ float g_Mf[BB*CIN*CIN];                                   // M fp32 (k rows, cc contig)
__device__ bf16 g_Mkh[BB*CIN*CIN], g_Mkm[BB*CIN*CIN];                // M (k rows, cc contig)
__device__ bf16 g_Mch[BB*CIN*CIN], g_Mcm[BB*CIN*CIN];                // (M+I)^T (cc rows, k contig)
__device__ bf16 g_M2h[BB*DD*CIN], g_M2m[BB*DD*CIN];                  // M2^T (d rows, k contig)
__device__ float g_b2e[BB*CIN];                                      // b2 + Wf·bg
__device__ float g_b3e[BB*DD];                                       // W3·b2e + b3
__device__ float g_sx[BB*CIN];
__device__ float g_bth[BB*C1], g_bph[BB*C1];
__device__ float g_Eacc[BB*KK*DD], g_Asum[BB*KK], g_Es[BB*DD], g_gam[BB*CIN];

// ------------- helpers -------------
__device__ __forceinline__ u32 smem_u32(const void* p) {
    u32 a;
    asm("{ .reg .u64 t; cvta.to.shared.u64 t, %1; cvt.u32.u64 %0, t; }" : "=r"(a) : "l"(p));
    return a;
}
__device__ __forceinline__ void cp16(u32 d, const void* s) {
    asm volatile("cp.async.cg.shared.global [%0], [%1], 16;" :: "r"(d), "l"(s));
}
__device__ __forceinline__ void cp_commit() { asm volatile("cp.async.commit_group;" ::: "memory"); }
template<int N> __device__ __forceinline__ void cp_waitg() {
    asm volatile("cp.async.wait_group %0;" :: "n"(N) : "memory");
}
__device__ __forceinline__ void ldm_x4(u32* r, u32 addr) {
    asm volatile("ldmatrix.sync.aligned.m8n8.x4.shared.b16 {%0,%1,%2,%3}, [%4];"
        : "=r"(r[0]), "=r"(r[1]), "=r"(r[2]), "=r"(r[3]) : "r"(addr));
}
__device__ __forceinline__ void ldm_x4t(u32* r, u32 addr) {
    asm volatile("ldmatrix.sync.aligned.m8n8.x4.trans.shared.b16 {%0,%1,%2,%3}, [%4];"
        : "=r"(r[0]), "=r"(r[1]), "=r"(r[2]), "=r"(r[3]) : "r"(addr));
}
__device__ __forceinline__ void mma16816(float* d, const u32* a, const u32* b) {
    asm volatile(
        "mma.sync.aligned.m16n8k16.row.col.f32.bf16.bf16.f32 "
        "{%0,%1,%2,%3}, {%4,%5,%6,%7}, {%8,%9}, {%0,%1,%2,%3};"
        : "+f"(d[0]), "+f"(d[1]), "+f"(d[2]), "+f"(d[3])
        : "r"(a[0]), "r"(a[1]), "r"(a[2]), "r"(a[3]), "r"(b[0]), "r"(b[1]));
}
__device__ __forceinline__ void st2bf(bf16* p, long i, float a, float b_) {
    __nv_bfloat162 v(__float2bfloat16(a), __float2bfloat16(b_));
    *(u32*)(p + i) = *(u32*)&v;
}

// ============ mma.sync bf16-split GEMM, product-shared tiles, BK=32 ============
// BTR=1: B operand stored (k rows, n contig) with 256B rows; loaded via ldmatrix.trans.
template<int NPROD, bool SYM, int NSTG, int BTR>
__global__ __launch_bounds__(256, 2) void mma_gemm(
    const bf16* __restrict__ Ah, const bf16* __restrict__ Am, const bf16* __restrict__ Al,
    int lda, long sAb,
    const bf16* __restrict__ Bh, const bf16* __restrict__ Bm, const bf16* __restrict__ Bl,
    int ldb, long sBb,
    float* __restrict__ C, bf16* __restrict__ Ch, bf16* __restrict__ Cm,
    int ldc, long sCz,
    const float* __restrict__ biasC, long sBC,
    const float* __restrict__ biasR, long sBR,
    const float* __restrict__ Rf, long sRz,
    const float* __restrict__ scaleR, long sSR,
    int NCH, int S)
{
    constexpr int NA = (NPROD == 6) ? 3 : 2;
    constexpr int NB = NA;
    constexpr int STAGE = (NA + NB) * 8192;

    extern __shared__ __align__(16) char smem[];
    const u32 sbase = smem_u32(smem);

    const int tid = threadIdx.x, lane = tid & 31, wid = tid >> 5;
    const int wm = wid & 1, wn = wid >> 1;
    const int z = blockIdx.z, b = z / S, s = z % S;
    int bx, by;
    if (SYM) {
        int p = blockIdx.x;
        by = (p < 1) ? 0 : (p < 3) ? 1 : (p < 6) ? 2 : 3;
        bx = p - (by * (by + 1)) / 2;
    } else { bx = blockIdx.x; by = blockIdx.y; }
    const long m0 = (long)by * 128;
    const int n0 = bx * 128;
    const int KS = NCH * 32;

    const long abase = (long)b * sAb + m0 * lda + (long)s * KS;
    const long bbase = BTR ? ((long)b * sBb + n0 + (long)s * KS * ldb)
                           : ((long)b * sBb + (long)n0 * ldb + (long)s * KS);

    const bf16* APT[3] = {Ah, Am, Al};
    const bf16* BPT[3] = {Bh, Bm, Bl};

    float acc[4][4][4];
#pragma unroll
    for (int i = 0; i < 4; i++)
#pragma unroll
        for (int j = 0; j < 4; j++)
#pragma unroll
            for (int r = 0; r < 4; r++) acc[i][j][r] = 0.f;

    const int row2 = tid >> 1, lq = tid & 1;
    const int sw = (row2 >> 1) & 3;
    const u32 c0off = (u32)(row2 * 64 + (((lq * 2 + 0) ^ sw) << 4));
    const u32 c1off = (u32)(row2 * 64 + (((lq * 2 + 1) ^ sw) << 4));
    // trans-tile store offsets: 32 rows(k) x 256B(n); chunk j -> j ^ (row&7)
    const int rowT = tid >> 3, jqT = tid & 7;
    const u32 t0off = (u32)(rowT * 256 + (((jqT * 2 + 0) ^ (rowT & 7)) << 4));
    const u32 t1off = (u32)(rowT * 256 + (((jqT * 2 + 1) ^ (rowT & 7)) << 4));

    auto issue = [&](int c) {
        int k0 = c * 32;
        u32 sd = sbase + (c % NSTG) * STAGE;
#pragma unroll
        for (int p = 0; p < NA; p++) {
            const bf16* ap = APT[p] + abase + k0 + (long)row2 * lda + lq * 16;
            cp16(sd + p * 8192 + c0off, ap);
            cp16(sd + p * 8192 + c1off, ap + 8);
        }
#pragma unroll
        for (int p = 0; p < NB; p++) {
            if (BTR) {
                const bf16* bp = BPT[p] + bbase + (long)(k0 + rowT) * ldb + jqT * 16;
                cp16(sd + (NA + p) * 8192 + t0off, bp);
                cp16(sd + (NA + p) * 8192 + t1off, bp + 8);
            } else {
                const bf16* bp = BPT[p] + bbase + k0 + (long)row2 * ldb + lq * 16;
                cp16(sd + (NA + p) * 8192 + c0off, bp);
                cp16(sd + (NA + p) * 8192 + c1off, bp + 8);
            }
        }
        cp_commit();
    };

    u32 aoff[4], boff[2];
#pragma unroll
    for (int t = 0; t < 4; t++) {
        int ra = wm * 64 + t * 16 + (lane & 15);
        int j = lane >> 4;
        aoff[t] = (u32)(ra * 64 + ((j ^ ((ra >> 1) & 3)) << 4));
    }
#pragma unroll
    for (int u = 0; u < 2; u++) {
        if (BTR) {
            int row = (lane & 7) + ((lane >> 3) & 1) * 8;   // k within 16
            int nchunk = wn * 4 + u * 2 + ((lane >> 4) & 1);
            boff[u] = (u32)(row * 256 + ((nchunk ^ (row & 7)) << 4));
        } else {
            int rb = wn * 32 + u * 16 + (lane & 7) + ((lane >> 4) & 1) * 8;
            int j = (lane >> 3) & 1;
            boff[u] = (u32)(rb * 64 + ((j ^ ((rb >> 1) & 3)) << 4));
        }
    }

#pragma unroll
    for (int p = 0; p < NSTG - 1; p++) if (p < NCH) issue(p);

    for (int c = 0; c < NCH; c++) {
        if (c + NSTG - 1 < NCH) { issue(c + NSTG - 1); cp_waitg<NSTG - 1>(); }
        else if (NSTG == 3 && c + 1 < NCH) cp_waitg<1>();
        else cp_waitg<0>();
        __syncthreads();
        u32 sA = sbase + (c % NSTG) * STAGE;
        u32 sB = sA + NA * 8192;
#pragma unroll
        for (int kk = 0; kk < 2; kk++) {
            u32 kx = kk << 5;
            u32 bfr[NB][2][4];
#pragma unroll
            for (int pb = 0; pb < NB; pb++)
#pragma unroll
                for (int u = 0; u < 2; u++) {
                    if (BTR) ldm_x4t(bfr[pb][u], sB + pb * 8192 + boff[u] + kk * 4096);
                    else     ldm_x4 (bfr[pb][u], sB + pb * 8192 + (boff[u] ^ kx));
                }
#pragma unroll
            for (int pa = 0; pa < NA; pa++) {
                u32 af[4][4];
#pragma unroll
                for (int t = 0; t < 4; t++)
                    ldm_x4(af[t], sA + pa * 8192 + (aoff[t] ^ kx));
#pragma unroll
                for (int pb = 0; pb < NB; pb++) {
                    if (pa + pb < NB) {
#pragma unroll
                        for (int mi = 0; mi < 4; mi++)
#pragma unroll
                            for (int ni = 0; ni < 4; ni++)
                                mma16816(acc[mi][ni], af[mi], &bfr[pb][ni >> 1][(ni & 1) * 2]);
                    }
                }
            }
        }
        __syncthreads();
    }

    // ---- epilogue ----
    const int mrow = lane >> 2, nc2 = (lane & 3) * 2;
#pragma unroll
    for (int mi = 0; mi < 4; mi++) {
#pragma unroll
        for (int rp = 0; rp < 2; rp++) {
            long row = m0 + wm * 64 + mi * 16 + mrow + rp * 8;
            long coff = (long)z * sCz + row * ldc;
            long roff = (long)b * sRz + row * ldc;
            float br = biasR ? biasR[b * sBR + row] : 0.f;
            float sr = scaleR ? scaleR[b * sSR + row] : 1.f;
#pragma unroll
            for (int ni = 0; ni < 4; ni++) {
                int col = n0 + wn * 32 + ni * 8 + nc2;
                float v0 = acc[mi][ni][rp * 2 + 0] + br;
                float v1 = acc[mi][ni][rp * 2 + 1] + br;
                if (biasC) { v0 += biasC[b * sBC + col]; v1 += biasC[b * sBC + col + 1]; }
                if (Rf) {
                    float2 r = *(const float2*)&Rf[roff + col];
                    v0 += r.x; v1 += r.y;
                }
                v0 *= sr; v1 *= sr;
                if (C) *(float2*)&C[coff + col] = make_float2(v0, v1);
                if (Ch) {
                    float h0 = __bfloat162float(__float2bfloat16(v0));
                    float h1 = __bfloat162float(__float2bfloat16(v1));
                    st2bf(Ch, coff + col, v0, v1);
                    st2bf(Cm, coff + col, v0 - h0, v1 - h1);
                }
            }
        }
    }
}

// ============ fused z_ GEMM + Deep-TEN encode (A = Xch via ldmatrix.trans) ============
__global__ __launch_bounds__(256, 2) void zde_kernel(
    const bf16* __restrict__ Ah, const bf16* __restrict__ Am,   // Xch h/m
    const bf16* __restrict__ Bh, const bf16* __restrict__ Bm,   // M2^T h/m
    const float* __restrict__ b3e,
    const float* __restrict__ codewords, const float* __restrict__ scale,
    float* __restrict__ Eacc, float* __restrict__ Asum)
{
    constexpr int STAGE = 32768;
    extern __shared__ __align__(16) char smem[];
    const u32 sbase = smem_u32(smem);
    float* zs = (float*)smem;                    // [128][129]
    float* cs = (float*)(smem + 66048);          // [32][129]
    float* cn = (float*)(smem + 82560);
    float* sc = cn + 32;
    float* Ash = sc + 32;

    const int tid = threadIdx.x, lane = tid & 31, wid = tid >> 5;
    const int wm = wid & 1, wn = wid >> 1;
    const int b = blockIdx.y;
    const long m0 = (long)blockIdx.x * 128;

    const long abase = (long)b * CIN * NN + m0;      // Xch: rows k=ch, n contig
    const long bbase = (long)b * (DD * CIN);

    float acc[4][4][4];
#pragma unroll
    for (int i = 0; i < 4; i++)
#pragma unroll
        for (int j = 0; j < 4; j++)
#pragma unroll
            for (int r = 0; r < 4; r++) acc[i][j][r] = 0.f;

    const int row2 = tid >> 1, lq = tid & 1;
    const int sw2 = (row2 >> 1) & 3;
    const u32 c0off = (u32)(row2 * 64 + (((lq * 2 + 0) ^ sw2) << 4));
    const u32 c1off = (u32)(row2 * 64 + (((lq * 2 + 1) ^ sw2) << 4));
    const int rowT = tid >> 3, jqT = tid & 7;
    const u32 t0off = (u32)(rowT * 256 + (((jqT * 2 + 0) ^ (rowT & 7)) << 4));
    const u32 t1off = (u32)(rowT * 256 + (((jqT * 2 + 1) ^ (rowT & 7)) << 4));

    auto issue = [&](int c) {
        int k0 = c * 32;
        u32 sd = sbase + (c % 3) * STAGE;
        // A = X trans tiles (32 k-rows x 256B)
        const bf16* a0 = Ah + abase + (long)(k0 + rowT) * NN + jqT * 16;
        const bf16* a1 = Am + abase + (long)(k0 + rowT) * NN + jqT * 16;
        cp16(sd + t0off, a0);            cp16(sd + t1off, a0 + 8);
        cp16(sd + 8192 + t0off, a1);     cp16(sd + 8192 + t1off, a1 + 8);
        // B = M2 standard (128 d-rows x 64B)
        const bf16* b0 = Bh + bbase + k0 + (long)row2 * CIN + lq * 16;
        const bf16* b1 = Bm + bbase + k0 + (long)row2 * CIN + lq * 16;
        cp16(sd + 16384 + c0off, b0);    cp16(sd + 16384 + c1off, b0 + 8);
        cp16(sd + 24576 + c0off, b1);    cp16(sd + 24576 + c1off, b1 + 8);
        cp_commit();
    };

    // trans-A ldmatrix offsets: a0=(m0-7,k0-7) a1=(m8-15,k0-7) a2=(m0-7,k8-15) a3=(m8-15,k8-15)
    u32 aoffT[4], boff[2];
#pragma unroll
    for (int t = 0; t < 4; t++) {
        int row = (lane & 7) + ((lane >> 4) & 1) * 8;           // k within 16
        int mchunk = wm * 8 + t * 2 + ((lane >> 3) & 1);
        aoffT[t] = (u32)(row * 256 + ((mchunk ^ (row & 7)) << 4));
    }
#pragma unroll
    for (int u = 0; u < 2; u++) {
        int rb = wn * 32 + u * 16 + (lane & 7) + ((lane >> 4) & 1) * 8;
        int j = (lane >> 3) & 1;
        boff[u] = (u32)(rb * 64 + ((j ^ ((rb >> 1) & 3)) << 4));
    }

    issue(0); issue(1);
    for (int c = 0; c < 16; c++) {
        if (c + 2 < 16) { issue(c + 2); cp_waitg<2>(); }
        else if (c + 1 < 16) cp_waitg<1>();
        else cp_waitg<0>();
        __syncthreads();
        u32 sA = sbase + (c % 3) * STAGE;
        u32 sB = sA + 16384;
#pragma unroll
        for (int kk = 0; kk < 2; kk++) {
            u32 kx = kk << 5;
            u32 bfr[2][2][4];
#pragma unroll
            for (int pb = 0; pb < 2; pb++)
#pragma unroll
                for (int u = 0; u < 2; u++)
                    ldm_x4(bfr[pb][u], sB + pb * 8192 + (boff[u] ^ kx));
#pragma unroll
            for (int pa = 0; pa < 2; pa++) {
                u32 af[4][4];
#pragma unroll
                for (int t = 0; t < 4; t++)
                    ldm_x4t(af[t], sA + pa * 8192 + aoffT[t] + kk * 4096);
#pragma unroll
                for (int pb = 0; pb < 2; pb++) {
                    if (pa + pb < 2) {
#pragma unroll
                        for (int mi = 0; mi < 4; mi++)
#pragma unroll
                            for (int ni = 0; ni < 4; ni++)
                                mma16816(acc[mi][ni], af[mi], &bfr[pb][ni >> 1][(ni & 1) * 2]);
                    }
                }
            }
        }
        __syncthreads();
    }

    // ---- stage z_ tile into smem ----
    const int mrow = lane >> 2, nc2 = (lane & 3) * 2;
#pragma unroll
    for (int mi = 0; mi < 4; mi++) {
#pragma unroll
        for (int rp = 0; rp < 2; rp++) {
            int row = wm * 64 + mi * 16 + mrow + rp * 8;
#pragma unroll
            for (int ni = 0; ni < 4; ni++) {
                int col = wn * 32 + ni * 8 + nc2;
                zs[row * 129 + col]     = acc[mi][ni][rp * 2 + 0] + b3e[b * DD + col];
                zs[row * 129 + col + 1] = acc[mi][ni][rp * 2 + 1] + b3e[b * DD + col + 1];
            }
        }
    }
    for (int i = tid; i < KK * DD; i += 256) cs[(i >> 7) * 129 + (i & 127)] = codewords[i];
    if (tid < KK) sc[tid] = scale[tid];
    __syncthreads();
    if (tid < KK) {
        float s = 0.f;
        for (int d = 0; d < DD; d++) { float c = cs[tid * 129 + d]; s += c * c; }
        cn[tid] = s;
    }
    __syncthreads();

    float ereg[16];
#pragma unroll
    for (int i = 0; i < 16; i++) ereg[i] = 0.f;
    float asum_local = 0.f;
    int myk = tid >> 3, myd0 = tid & 7;

    for (int round = 0; round < 16; round++) {
        int n = round * 8 + wid;
        float xx = 0.f;
        for (int d = lane; d < DD; d += 32) { float x = zs[n * 129 + d]; xx += x * x; }
        for (int o = 16; o; o >>= 1) xx += __shfl_xor_sync(0xffffffffu, xx, o);
        float dot = 0.f;
#pragma unroll 8
        for (int d = 0; d < DD; d++) dot += zs[n * 129 + d] * cs[lane * 129 + d];
        float s = sc[lane] * (xx - 2.f * dot + cn[lane]);
        float mx = s;
        for (int o = 16; o; o >>= 1) mx = fmaxf(mx, __shfl_xor_sync(0xffffffffu, mx, o));
        float e = __expf(s - mx);
        float ssum = e;
        for (int o = 16; o; o >>= 1) ssum += __shfl_xor_sync(0xffffffffu, ssum, o);
        float a = e / ssum;
        Ash[wid * 32 + lane] = a;
        asum_local += a;
        __syncthreads();
#pragma unroll
        for (int nn2 = 0; nn2 < 8; nn2++) {
            float av = Ash[nn2 * 32 + myk];
            int ncol = round * 8 + nn2;
#pragma unroll
            for (int i = 0; i < 16; i++)
                ereg[i] += av * zs[ncol * 129 + myd0 + 8 * i];
        }
        __syncthreads();
    }
#pragma unroll
    for (int i = 0; i < 16; i++)
        atomicAdd(&Eacc[((long)b * KK + myk) * DD + myd0 + 8 * i], ereg[i]);
    atomicAdd(&Asum[b * KK + lane], asum_local);
}

// ------------- X split (C-major only) h/m/l + row sums -------------
__global__ void csplit(const float* __restrict__ src)
{
    long idx4 = (long)blockIdx.x * 256 + threadIdx.x;   // over 9.4M float4
    const long total4 = (long)ROWS * CIN / 4;
    if (idx4 >= total4) return;
    long e0 = idx4 * 4;
    float4 v = ((const float4*)src)[idx4];
    float vv[4] = {v.x, v.y, v.z, v.w};
    bf16 h4[4], m4[4], l4[4];
    float sum = 0.f;
#pragma unroll
    for (int i = 0; i < 4; i++) {
        float x = vv[i];
        sum += x;
        bf16 h = __float2bfloat16(x);
        float r1 = x - __bfloat162float(h);
        bf16 m = __float2bfloat16(r1);
        h4[i] = h; m4[i] = m;
        l4[i] = __float2bfloat16(r1 - __bfloat162float(m));
    }
    *(ulonglong1*)&g_Xch[e0] = *(ulonglong1*)h4;
    *(ulonglong1*)&g_Xcm[e0] = *(ulonglong1*)m4;
    *(ulonglong1*)&g_Xcl[e0] = *(ulonglong1*)l4;
    // warp covers 128 consecutive floats of one (b,ch) row (9216 % 128 == 0)
#pragma unroll
    for (int off = 16; off; off >>= 1) sum += __shfl_xor_sync(0xffffffffu, sum, off);
    if ((threadIdx.x & 31) == 0) {
        long bc = e0 / NN;           // b*CIN + ch
        atomicAdd(&g_sx[bc], sum);
    }
}

// ------------- weight splits + accumulator zeroing -------------
__global__ void split_all(const float* __restrict__ Wt, const float* __restrict__ Wp,
                          const float* __restrict__ Wg, const float* __restrict__ W2,
                          const float* __restrict__ W3)
{
    int i = blockIdx.x * 256 + threadIdx.x;
    if (i < BB * KK * DD) g_Eacc[i] = 0.f;
    if (i < BB * KK)      g_Asum[i] = 0.f;
    if (i < BB * DD)      g_Es[i]   = 0.f;
    if (i < BB * CIN)     g_sx[i]   = 0.f;
    if (i < C1 * CIN) {
        float v = Wt[i];
        bf16 h = __float2bfloat16(v); float r1 = v - __bfloat162float(h);
        bf16 m = __float2bfloat16(r1);
        g_Wth[i] = h; g_Wtm[i] = m; g_Wtl[i] = __float2bfloat16(r1 - __bfloat162float(m));
        v = Wp[i];
        h = __float2bfloat16(v); r1 = v - __bfloat162float(h);
        m = __float2bfloat16(r1);
        g_Wph[i] = h; g_Wpm[i] = m; g_Wpl[i] = __float2bfloat16(r1 - __bfloat162float(m));
        v = Wg[i];
        int d = i >> 9, k = i & 511;
        h = __float2bfloat16(v);
        g_WgTh[k * C1 + d] = h;
        g_WgTm[k * C1 + d] = __float2bfloat16(v - __bfloat162float(h));
        v = W2[i];
        h = __float2bfloat16(v);
        g_W2h[i] = h; g_W2m[i] = __float2bfloat16(v - __bfloat162float(h));
    }
    if (i < DD * CIN) {
        float v = W3[i];
        bf16 h = __float2bfloat16(v);
        g_W3h[i] = h; g_W3m[i] = __float2bfloat16(v - __bfloat162float(h));
    }
}

// ------------- reduce Gram split-K partials (triangle-only reads, mirror writes) -------------
__global__ void gram_reduce()
{
    long idx = (long)blockIdx.x * 256 + threadIdx.x;
    int b = (int)(idx >> 18);
    int rem = (int)(idx & 262143);
    int c1 = rem >> 9, c2 = rem & 511;
    int t1 = c1 >> 7, t2 = c2 >> 7;
    if (t1 < t2) return;
    float v = 0.f;
#pragma unroll
    for (int s = 0; s < GS; s++) v += g_Gp[(((long)(b * GS + s)) << 18) + (long)rem];
    bf16 h = __float2bfloat16(v);
    float r1 = v - __bfloat162float(h);
    bf16 m = __float2bfloat16(r1);
    bf16 l = __float2bfloat16(r1 - __bfloat162float(m));
    g_GRh[idx] = h; g_GRm[idx] = m; g_GRl[idx] = l;
    if (t1 > t2) {
        long mdx = (((long)b) << 18) + ((long)c2 << 9) + c1;
        g_GRh[mdx] = h; g_GRm[mdx] = m; g_GRl[mdx] = l;
    }
}

// ------------- reduce T1 split-K partials + 3-way split -------------
__global__ void t1_reduce()
{
    long idx = (long)blockIdx.x * 256 + threadIdx.x;
    int b = (int)(idx >> 17);
    long il = idx & 131071;
    float v = 0.f;
#pragma unroll
    for (int s = 0; s < 4; s++) v += g_T1p[(((long)(b * 4 + s)) << 17) + il];
    bf16 h = __float2bfloat16(v);
    float r1 = v - __bfloat162float(h);
    bf16 m = __float2bfloat16(r1);
    g_T1h[idx] = h; g_T1m[idx] = m;
    g_T1l[idx] = __float2bfloat16(r1 - __bfloat162float(m));
}

// ------------- M split: Mk = M (k rows), Mc = (M+I)^T (cc rows) -------------
__global__ void msplit()
{
    long idx = (long)blockIdx.x * 256 + threadIdx.x;
    int b = (int)(idx >> 18);
    int rem = (int)(idx & 262143);
    int k = rem >> 9, cc = rem & 511;
    float v = g_Mf[idx];
    bf16 h = __float2bfloat16(v);
    bf16 m = __float2bfloat16(v - __bfloat162float(h));
    g_Mkh[idx] = h; g_Mkm[idx] = m;
    float v2 = v + (k == cc ? 1.f : 0.f);
    bf16 h2 = __float2bfloat16(v2);
    bf16 m2 = __float2bfloat16(v2 - __bfloat162float(h2));
    long tdx = (((long)b) << 18) + ((long)cc << 9) + k;
    g_Mch[tdx] = h2; g_Mcm[tdx] = m2;
}

// ------------- bias rank-1 corrections -------------
__global__ void bcorr(const float* __restrict__ Wt, const float* __restrict__ Wp)
{
    int idx = blockIdx.x * 256 + threadIdx.x;
    int which = idx >> 11;
    int r = idx & 2047;
    int b = r >> 8, c = r & 255;
    const float* W = which ? Wp : Wt;
    float s = 0.f;
    for (int k = 0; k < CIN; k++) s += W[c * CIN + k] * g_sx[b * CIN + k];
    (which ? g_bph : g_bth)[b * C1 + c] = s;
}

// ------------- b2e = b2 + Wf·bg -------------
__global__ void b2e_kernel(const float* __restrict__ b2, const float* __restrict__ bg)
{
    int idx = blockIdx.x * 256 + threadIdx.x;
    int b = idx >> 9, c = idx & 511;
    float s = b2[c];
    long base = ((long)b << 17) + (long)c * C1;
    for (int d = 0; d < C1; d++)
        s += bg[d] * (__bfloat162float(g_Wfh[base + d]) + __bfloat162float(g_Wfm[base + d]));
    g_b2e[idx] = s;
}

// ------------- b3e = W3·b2e + b3 -------------
__global__ void b3e_kernel(const float* __restrict__ W3, const float* __restrict__ b3)
{
    int idx = blockIdx.x * 256 + threadIdx.x;
    int b = idx >> 7, d = idx & 127;
    float s = b3[d];
    for (int c = 0; c < CIN; c++) s += g_b2e[b * CIN + c] * W3[d * CIN + c];
    g_b3e[idx] = s;
}

// ------------- softmax over f rows, f^T bf16 out -------------
__global__ void softmaxT(const float* __restrict__ bth_bias, const float* __restrict__ bph_bias)
{
    int row = blockIdx.x, t = threadIdx.x;
    int b = row >> 8, c = row & 255;
    long il = (long)c * 256 + t;
    float v = 0.f;
#pragma unroll
    for (int s = 0; s < 4; s++) v += g_Fp4[(((long)(b * 4 + s)) << 16) + il];
    v += bth_bias[c] * g_bph[b * C1 + t]
       + bph_bias[t] * g_bth[b * C1 + c]
       + (float)NN * bth_bias[c] * bph_bias[t];
    __shared__ float sh[256];
    sh[t] = v; __syncthreads();
    for (int o = 128; o; o >>= 1) { if (t < o) sh[t] = fmaxf(sh[t], sh[t + o]); __syncthreads(); }
    float mx = sh[0]; __syncthreads();
    float e = expf(v - mx);
    sh[t] = e; __syncthreads();
    for (int o = 128; o; o >>= 1) { if (t < o) sh[t] += sh[t + o]; __syncthreads(); }
    float r = e / sh[0];
    long o2 = ((long)b << 16) + (long)t * 256 + c;
    bf16 h = __float2bfloat16(r);
    g_Fh[o2] = h;
    g_Fm[o2] = __float2bfloat16(r - __bfloat162float(h));
}

// ------------- BN over K + Es -------------
__global__ void bn_es_kernel(const float* __restrict__ Eacc, const float* __restrict__ Asum,
                             const float* __restrict__ codewords, float* __restrict__ Es)
{
    int k = blockIdx.x, tid = threadIdx.x;
    __shared__ double shs[256], shs2[256];
    float vals[4];
    double s = 0.0, s2 = 0.0;
#pragma unroll
    for (int i = 0; i < 4; i++) {
        int idx = tid + i * 256;
        int b = idx >> 7, d = idx & 127;
        float v = Eacc[((long)b * KK + k) * DD + d] - Asum[b * KK + k] * codewords[k * DD + d];
        vals[i] = v; s += v; s2 += (double)v * v;
    }
    shs[tid] = s; shs2[tid] = s2; __syncthreads();
    for (int o = 128; o; o >>= 1) {
        if (tid < o) { shs[tid] += shs[tid + o]; shs2[tid] += shs2[tid + o]; }
        __syncthreads();
    }
    double mean = shs[0] / 1024.0;
    double var = shs2[0] / 1024.0 - mean * mean;
    float inv = rsqrtf((float)var + 1e-5f);
    float mf = (float)mean;
#pragma unroll
    for (int i = 0; i < 4; i++) {
        int idx = tid + i * 256;
        int b = idx >> 7, d = idx & 127;
        float e = (vals[i] - mf) * inv;
        if (e > 0.f) atomicAdd(&Es[b * DD + d], e);
    }
}

// ------------- gamma = sigmoid(Es @ W_fc^T + b_fc) -------------
__global__ void gamma_kernel(const float* __restrict__ Es, const float* __restrict__ W_fc,
                             const float* __restrict__ b_fc, float* __restrict__ gam)
{
    int idx = blockIdx.x * blockDim.x + threadIdx.x;
    int b = idx / CIN, c = idx % CIN;
    float s = b_fc[c];
    for (int d = 0; d < DD; d++) s += Es[b * DD + d] * W_fc[c * DD + d];
    gam[idx] = 1.f / (1.f + expf(-s));
}

// ------------- launch -------------
#define GA(T, p, s) T* p; cudaGetSymbolAddress((void**)&p, s)

extern "C" void kernel_launch(void* const* d_in, const int* in_sizes, int n_in,
                              void* d_out, int out_size)
{
    const float* X        = (const float*)d_in[0];
    const float* W_theta  = (const float*)d_in[1];
    const float* b_theta  = (const float*)d_in[2];
    const float* W_phi    = (const float*)d_in[3];
    const float* b_phi    = (const float*)d_in[4];
    const float* W_g      = (const float*)d_in[5];
    const float* b_g      = (const float*)d_in[6];
    const float* W2       = (const float*)d_in[7];
    const float* b2       = (const float*)d_in[8];
    const float* W3       = (const float*)d_in[9];
    const float* b3       = (const float*)d_in[10];
    const float* codewords= (const float*)d_in[11];
    const float* scale    = (const float*)d_in[12];
    const float* W_fc     = (const float*)d_in[13];
    const float* b_fc     = (const float*)d_in[14];

    GA(bf16, Xch, g_Xch); GA(bf16, Xcm, g_Xcm); GA(bf16, Xcl, g_Xcl);
    GA(bf16, Wth, g_Wth); GA(bf16, Wtm, g_Wtm); GA(bf16, Wtl, g_Wtl);
    GA(bf16, Wph, g_Wph); GA(bf16, Wpm, g_Wpm); GA(bf16, Wpl, g_Wpl);
    GA(bf16, WgTh, g_WgTh); GA(bf16, WgTm, g_WgTm);
    GA(bf16, W2h, g_W2h); GA(bf16, W2m, g_W2m);
    GA(bf16, W3h, g_W3h); GA(bf16, W3m, g_W3m);
    GA(float, Gp, g_Gp);
    GA(bf16, GRh, g_GRh); GA(bf16, GRm, g_GRm); GA(bf16, GRl, g_GRl);
    GA(float, T1p, g_T1p);
    GA(bf16, T1h, g_T1h); GA(bf16, T1m, g_T1m); GA(bf16, T1l, g_T1l);
    GA(float, Fp4, g_Fp4);
    GA(bf16, Fh, g_Fh); GA(bf16, Fm, g_Fm);
    GA(bf16, Wfh, g_Wfh); GA(bf16, Wfm, g_Wfm);
    GA(float, Mf, g_Mf);
    GA(bf16, Mkh, g_Mkh); GA(bf16, Mkm, g_Mkm);
    GA(bf16, Mch, g_Mch); GA(bf16, Mcm, g_Mcm);
    GA(bf16, M2h, g_M2h); GA(bf16, M2m, g_M2m);
    GA(float, b2e, g_b2e); GA(float, b3e, g_b3e);
    GA(float, Eacc, g_Eacc); GA(float, Asum, g_Asum);
    GA(float, Es, g_Es); GA(float, gamB, g_gam);

    const int SMEM6 = 2 * 6 * 8192;   // 98304
    const int SMEM3 = 3 * 4 * 8192;   // 98304
    cudaFuncSetAttribute((const void*)mma_gemm<6, false, 2, 0>, cudaFuncAttributeMaxDynamicSharedMemorySize, SMEM6);
    cudaFuncSetAttribute((const void*)mma_gemm<6, true, 2, 0>,  cudaFuncAttributeMaxDynamicSharedMemorySize, SMEM6);
    cudaFuncSetAttribute((const void*)mma_gemm<3, false, 3, 0>, cudaFuncAttributeMaxDynamicSharedMemorySize, SMEM3);
    cudaFuncSetAttribute((const void*)mma_gemm<3, false, 3, 1>, cudaFuncAttributeMaxDynamicSharedMemorySize, SMEM3);
    cudaFuncSetAttribute((const void*)zde_kernel, cudaFuncAttributeMaxDynamicSharedMemorySize, SMEM3);

    split_all<<<512, 256>>>(W_theta, W_phi, W_g, W2, W3);
    csplit<<<36864, 256>>>(X);

    // Gram: G = X·X^T per batch, lower-triangle tiles, split-K=18 (KS=512)
    mma_gemm<6, true, 2, 0><<<dim3(10, 1, BB * GS), 256, SMEM6>>>(
        Xch, Xcm, Xcl, NN, (long)CIN * NN, Xch, Xcm, Xcl, NN, (long)CIN * NN,
        Gp, nullptr, nullptr, CIN, (long)CIN * CIN,
        nullptr, 0, nullptr, 0, nullptr, 0, nullptr, 0, 16, GS);
    gram_reduce<<<8192, 256>>>();

    bcorr<<<16, 256>>>(W_theta, W_phi);

    // T1 = Wphi @ G (256x512/batch), x6, split-K=4
    mma_gemm<6, false, 2, 0><<<dim3(4, 2, BB * 4), 256, SMEM6>>>(
        Wph, Wpm, Wpl, CIN, 0, GRh, GRm, GRl, CIN, (long)CIN * CIN,
        T1p, nullptr, nullptr, CIN, 131072L,
        nullptr, 0, nullptr, 0, nullptr, 0, nullptr, 0, 4, 4);
    t1_reduce<<<4096, 256>>>();

    // f = Wtheta @ T1^T (256x256/batch), x6, split-K=4
    mma_gemm<6, false, 2, 0><<<dim3(2, 2, BB * 4), 256, SMEM6>>>(
        Wth, Wtm, Wtl, CIN, 0, T1h, T1m, T1l, CIN, 131072L,
        Fp4, nullptr, nullptr, C1, 65536L,
        nullptr, 0, nullptr, 0, nullptr, 0, nullptr, 0, 4, 4);

    softmaxT<<<BB * C1, 256>>>(b_theta, b_phi);

    // Wf = W2 @ f^T
    mma_gemm<3, false, 3, 0><<<dim3(2, 4, BB), 256, SMEM3>>>(
        W2h, W2m, nullptr, C1, 0, Fh, Fm, nullptr, C1, 65536L,
        nullptr, Wfh, Wfm, C1, 131072L,
        nullptr, 0, nullptr, 0, nullptr, 0, nullptr, 0, 8, 1);

    b2e_kernel<<<16, 256>>>(b2, b_g);
    b3e_kernel<<<4, 256>>>(W3, b3);

    // M[k,cc] = Wg^T · Wf^T
    mma_gemm<3, false, 3, 0><<<dim3(4, 4, BB), 256, SMEM3>>>(
        WgTh, WgTm, nullptr, C1, 0, Wfh, Wfm, nullptr, C1, 131072L,
        Mf, nullptr, nullptr, CIN, 262144L,
        nullptr, 0, nullptr, 0, nullptr, 0, nullptr, 0, 8, 1);
    msplit<<<8192, 256>>>();

    // M2^T[d,k] = W3 · (M+I)
    mma_gemm<3, false, 3, 0><<<dim3(4, 1, BB), 256, SMEM3>>>(
        W3h, W3m, nullptr, CIN, 0, Mkh, Mkm, nullptr, CIN, 262144L,
        nullptr, M2h, M2m, CIN, 65536L,
        nullptr, 0, nullptr, 0, W3, 0, nullptr, 0, 16, 1);

    // fused z_ + encode (A = Xch via ldmatrix.trans)
    zde_kernel<<<dim3(72, BB), 256, SMEM3>>>(
        Xch, Xcm, M2h, M2m, b3e, codewords, scale, Eacc, Asum);

    bn_es_kernel<<<KK, 256>>>(Eacc, Asum, codewords, Es);
    gamma_kernel<<<(BB * CIN) / 256, 256>>>(Es, W_fc, b_fc, gamB);

    // out (B,C,N): C[cc,n] = ((M+I)^T·X^T + b2e[cc]) * gamma[cc]
    // A = Mc (cc rows, k contig); B = Xch (k rows, n contig) via trans
    mma_gemm<3, false, 3, 1><<<dim3(72, 4, BB), 256, SMEM3>>>(
        Mch, Mcm, nullptr, CIN, 262144L, Xch, Xcm, nullptr, NN, (long)CIN * NN,
        (float*)d_out, nullptr, nullptr, NN, (long)CIN * NN,
        nullptr, 0, b2e, CIN, nullptr, 0, gamB, CIN, 16, 1);
}